// round 14
// baseline (speedup 1.0000x reference)
#include <cuda_runtime.h>
#include <cuda_bf16.h>
#include <cstdint>

#define B_  128
#define T_  512
#define G_  768
#define NS_ 64
#define M_  (B_*T_)
#define BTN_ (M_*NS_)
typedef unsigned long long ull;
typedef unsigned int uint32;
typedef unsigned short ushort_;

__device__ float d_emb_proj[512 * G_];
__device__ float d_xg2[(size_t)M_ * G_];
__device__ float d_h1[(size_t)M_ * 256];
__device__ float d_h2[(size_t)M_ * 256];
__device__ ushort_ d_h1hi[(size_t)M_ * 256];
__device__ ushort_ d_h1lo[(size_t)M_ * 256];
__device__ ushort_ d_wihhi[G_ * 256];
__device__ ushort_ d_wihlo[G_ * 256];
__device__ float2 d_lpart[256];
__device__ int g_mask_mode;

__device__ __forceinline__ ull ffma2(ull a, ull b, ull c) {
    ull d; asm("fma.rn.f32x2 %0, %1, %2, %3;" : "=l"(d) : "l"(a), "l"(b), "l"(c)); return d;
}
__device__ __forceinline__ ull dup2(float x) {
    ull d; asm("mov.b64 %0, {%1, %2};" : "=l"(d) : "f"(x), "f"(x)); return d;
}
__device__ __forceinline__ float lo32(ull v) { return __uint_as_float((unsigned)v); }
__device__ __forceinline__ float hi32(ull v) { return __uint_as_float((unsigned)(v >> 32)); }
__device__ __forceinline__ void cluster_sync_() {
    asm volatile("barrier.cluster.arrive.aligned;\n\tbarrier.cluster.wait.aligned;" ::: "memory");
}
__device__ __forceinline__ unsigned smem_u32(const void* p) {
    return (unsigned)__cvta_generic_to_shared(p);
}
__device__ __forceinline__ float tanhapx(float x) {
    float y; asm("tanh.approx.f32 %0, %1;" : "=f"(y) : "f"(x)); return y;
}

#define MMA16816(c, a0, a1, a2, a3, b0, b1) \
    asm volatile("mma.sync.aligned.m16n8k16.row.col.f32.bf16.bf16.f32 " \
                 "{%0,%1,%2,%3}, {%4,%5,%6,%7}, {%8,%9}, {%0,%1,%2,%3};" \
                 : "+f"((c)[0]), "+f"((c)[1]), "+f"((c)[2]), "+f"((c)[3]) \
                 : "r"(a0), "r"(a1), "r"(a2), "r"(a3), "r"(b0), "r"(b1))

__global__ void probe_mask_kernel(const unsigned char* __restrict__ m) {
    if (threadIdx.x == 0) {
        bool hasBig = false, offMult = false;
        for (int i = 0; i < 256; i++) {
            unsigned char c = m[i];
            if (c > 1) hasBig = true;
            if (c == 1 && (i & 3)) offMult = true;
        }
        g_mask_mode = hasBig ? 1 : (offMult ? 2 : 0);
    }
}

// ---------------- fp32 -> bf16 hi/lo split (elementwise) ----------------
__global__ void __launch_bounds__(256) cvt_split(const float* __restrict__ src,
                                                 ushort_* __restrict__ hi,
                                                 ushort_* __restrict__ lo, int n4) {
    int i = blockIdx.x * 256 + threadIdx.x;
    if (i >= n4) return;
    float4 v = *(const float4*)(src + (size_t)i * 4);
    ushort_ h[4], l[4];
    float f[4] = {v.x, v.y, v.z, v.w};
#pragma unroll
    for (int j = 0; j < 4; j++) {
        __nv_bfloat16 hb = __float2bfloat16_rn(f[j]);
        h[j] = __bfloat16_as_ushort(hb);
        l[j] = __bfloat16_as_ushort(__float2bfloat16_rn(f[j] - __bfloat162float(hb)));
    }
    *(uint2*)(hi + (size_t)i * 4) = make_uint2((uint32)h[0] | ((uint32)h[1] << 16),
                                               (uint32)h[2] | ((uint32)h[3] << 16));
    *(uint2*)(lo + (size_t)i * 4) = make_uint2((uint32)l[0] | ((uint32)l[1] << 16),
                                               (uint32)l[2] | ((uint32)l[3] << 16));
}

// ---------------- split-bf16 tensor-core GEMM (preconverted operands) ---------
#define BST 12
#define MATW (128 * BST)
#define BFS_SMEM (8 * MATW * 4)

__global__ void __launch_bounds__(256) gemm_bfs(const ushort_* __restrict__ Ahi,
                                                const ushort_* __restrict__ Alo,
                                                const ushort_* __restrict__ Bhi,
                                                const ushort_* __restrict__ Blo,
                                                float* __restrict__ C, int N) {
    extern __shared__ __align__(16) uint32 bsm[];
    uint32* Ah = bsm;
    uint32* Al = bsm + 2 * MATW;
    uint32* Bh = bsm + 4 * MATW;
    uint32* Bl = bsm + 6 * MATW;

    int tid = threadIdx.x;
    int m0 = blockIdx.y * 128, n0 = blockIdx.x * 128;
    int wid = tid >> 5, l = tid & 31;
    int wm = wid & 3, wn = wid >> 2;
    int lrow = tid >> 1, lhalf = tid & 1;   // loader mapping: 128 rows x 2 halves
    const ushort_* Ahg = Ahi + (size_t)m0 * 256;
    const ushort_* Alg = Alo + (size_t)m0 * 256;
    const ushort_* Bhg = Bhi + (size_t)n0 * 256;
    const ushort_* Blg = Blo + (size_t)n0 * 256;

    float c[16][4];
#pragma unroll
    for (int i = 0; i < 16; i++)
#pragma unroll
        for (int j = 0; j < 4; j++) c[i][j] = 0.f;

    size_t lsrc = (size_t)lrow * 256 + lhalf * 8;
    int ldst = lrow * BST + lhalf * 4;

    uint4 vah, val, vbh, vbl;
    vah = *(const uint4*)(Ahg + lsrc);
    val = *(const uint4*)(Alg + lsrc);
    vbh = *(const uint4*)(Bhg + lsrc);
    vbl = *(const uint4*)(Blg + lsrc);
    *(uint4*)&Ah[ldst] = vah;
    *(uint4*)&Al[ldst] = val;
    *(uint4*)&Bh[ldst] = vbh;
    *(uint4*)&Bl[ldst] = vbl;
    __syncthreads();

    int fr = l >> 2, kp = l & 3;
    for (int ch = 0; ch < 16; ch++) {
        int cur = ch & 1;
        uint32* Ahc = Ah + cur * MATW;
        uint32* Alc = Al + cur * MATW;
        uint32* Bhc = Bh + cur * MATW;
        uint32* Blc = Bl + cur * MATW;
        if (ch < 15) {
            size_t s = lsrc + (ch + 1) * 16;
            vah = *(const uint4*)(Ahg + s);
            val = *(const uint4*)(Alg + s);
            vbh = *(const uint4*)(Bhg + s);
            vbl = *(const uint4*)(Blg + s);
        }
        uint32 ah[2][4], al_[2][4];
#pragma unroll
        for (int mi = 0; mi < 2; mi++) {
            int r = wm * 32 + mi * 16 + fr;
            ah[mi][0] = Ahc[r * BST + kp];
            ah[mi][1] = Ahc[(r + 8) * BST + kp];
            ah[mi][2] = Ahc[r * BST + 4 + kp];
            ah[mi][3] = Ahc[(r + 8) * BST + 4 + kp];
            al_[mi][0] = Alc[r * BST + kp];
            al_[mi][1] = Alc[(r + 8) * BST + kp];
            al_[mi][2] = Alc[r * BST + 4 + kp];
            al_[mi][3] = Alc[(r + 8) * BST + 4 + kp];
        }
#pragma unroll
        for (int ni = 0; ni < 8; ni++) {
            int nr = wn * 64 + ni * 8 + fr;
            uint32 bh0 = Bhc[nr * BST + kp];
            uint32 bh1 = Bhc[nr * BST + 4 + kp];
            uint32 bl0 = Blc[nr * BST + kp];
            uint32 bl1 = Blc[nr * BST + 4 + kp];
#pragma unroll
            for (int mi = 0; mi < 2; mi++) {
                MMA16816(c[mi * 8 + ni], ah[mi][0], ah[mi][1], ah[mi][2], ah[mi][3], bh0, bh1);
                MMA16816(c[mi * 8 + ni], ah[mi][0], ah[mi][1], ah[mi][2], ah[mi][3], bl0, bl1);
                MMA16816(c[mi * 8 + ni], al_[mi][0], al_[mi][1], al_[mi][2], al_[mi][3], bh0, bh1);
            }
        }
        if (ch < 15) {
            int nxt = cur ^ 1;
            __syncthreads();
            *(uint4*)&Ah[nxt * MATW + ldst] = vah;
            *(uint4*)&Al[nxt * MATW + ldst] = val;
            *(uint4*)&Bh[nxt * MATW + ldst] = vbh;
            *(uint4*)&Bl[nxt * MATW + ldst] = vbl;
            __syncthreads();
        }
    }
#pragma unroll
    for (int mi = 0; mi < 2; mi++)
#pragma unroll
        for (int ni = 0; ni < 8; ni++) {
            int row = m0 + wm * 32 + mi * 16 + fr;
            int col = n0 + wn * 64 + ni * 8 + kp * 2;
            float2* p0 = (float2*)(C + (size_t)row * N + col);
            float2* p1 = (float2*)(C + (size_t)(row + 8) * N + col);
            *p0 = make_float2(c[mi * 8 + ni][0], c[mi * 8 + ni][1]);
            *p1 = make_float2(c[mi * 8 + ni][2], c[mi * 8 + ni][3]);
        }
}

// ---------------- GEMM 128x128 fp32 (emb-proj only) ----------------
#define GS 132
__global__ void __launch_bounds__(256) gemm128(const float* __restrict__ A,
                                               const float* __restrict__ Bm,
                                               float* __restrict__ C, int N) {
    __shared__ __align__(16) float As[2][16 * GS];
    __shared__ __align__(16) float Bs[2][16 * GS];
    int tid = threadIdx.x;
    int m0 = blockIdx.y * 128, n0 = blockIdx.x * 128;
    int tm = tid & 15, tn = tid >> 4;
    const float* Ag = A + (size_t)m0 * 256;
    const float* Bg = Bm + (size_t)n0 * 256;

    float4 ar[2], br[2];
#pragma unroll
    for (int j = 0; j < 2; j++) {
        int f = tid + j * 256;
        ar[j] = *(const float4*)(Ag + (size_t)(f >> 2) * 256 + (f & 3) * 4);
        br[j] = *(const float4*)(Bg + (size_t)(f >> 2) * 256 + (f & 3) * 4);
    }
#pragma unroll
    for (int j = 0; j < 2; j++) {
        int f = tid + j * 256; int row = f >> 2, kq = f & 3;
        As[0][(kq * 4 + 0) * GS + row] = ar[j].x;
        As[0][(kq * 4 + 1) * GS + row] = ar[j].y;
        As[0][(kq * 4 + 2) * GS + row] = ar[j].z;
        As[0][(kq * 4 + 3) * GS + row] = ar[j].w;
        Bs[0][(kq * 4 + 0) * GS + row] = br[j].x;
        Bs[0][(kq * 4 + 1) * GS + row] = br[j].y;
        Bs[0][(kq * 4 + 2) * GS + row] = br[j].z;
        Bs[0][(kq * 4 + 3) * GS + row] = br[j].w;
    }
    __syncthreads();

    ull acc[4][8];
#pragma unroll
    for (int i = 0; i < 4; i++)
#pragma unroll
        for (int j = 0; j < 8; j++) acc[i][j] = 0ull;

    for (int ch = 0; ch < 16; ch++) {
        int cur = ch & 1;
        if (ch < 15) {
#pragma unroll
            for (int j = 0; j < 2; j++) {
                int f = tid + j * 256;
                ar[j] = *(const float4*)(Ag + (size_t)(f >> 2) * 256 + (ch + 1) * 16 + (f & 3) * 4);
                br[j] = *(const float4*)(Bg + (size_t)(f >> 2) * 256 + (ch + 1) * 16 + (f & 3) * 4);
            }
        }
#pragma unroll
        for (int k = 0; k < 16; k++) {
            ulonglong2 a01 = *(const ulonglong2*)&As[cur][k * GS + tm * 8];
            ulonglong2 a23 = *(const ulonglong2*)&As[cur][k * GS + tm * 8 + 4];
            float4 bq0 = *(const float4*)&Bs[cur][k * GS + tn * 8];
            float4 bq1 = *(const float4*)&Bs[cur][k * GS + tn * 8 + 4];
            float bf[8] = {bq0.x, bq0.y, bq0.z, bq0.w, bq1.x, bq1.y, bq1.z, bq1.w};
#pragma unroll
            for (int j = 0; j < 8; j++) {
                ull bb = dup2(bf[j]);
                acc[0][j] = ffma2(a01.x, bb, acc[0][j]);
                acc[1][j] = ffma2(a01.y, bb, acc[1][j]);
                acc[2][j] = ffma2(a23.x, bb, acc[2][j]);
                acc[3][j] = ffma2(a23.y, bb, acc[3][j]);
            }
        }
        if (ch < 15) {
            int nxt = cur ^ 1;
#pragma unroll
            for (int j = 0; j < 2; j++) {
                int f = tid + j * 256; int row = f >> 2, kq = f & 3;
                As[nxt][(kq * 4 + 0) * GS + row] = ar[j].x;
                As[nxt][(kq * 4 + 1) * GS + row] = ar[j].y;
                As[nxt][(kq * 4 + 2) * GS + row] = ar[j].z;
                As[nxt][(kq * 4 + 3) * GS + row] = ar[j].w;
                Bs[nxt][(kq * 4 + 0) * GS + row] = br[j].x;
                Bs[nxt][(kq * 4 + 1) * GS + row] = br[j].y;
                Bs[nxt][(kq * 4 + 2) * GS + row] = br[j].z;
                Bs[nxt][(kq * 4 + 3) * GS + row] = br[j].w;
            }
            __syncthreads();
        }
    }
#pragma unroll
    for (int i = 0; i < 8; i++) {
        int mp = i >> 1;
        float4 v0, v1;
        if ((i & 1) == 0) {
            v0.x = lo32(acc[mp][0]); v0.y = lo32(acc[mp][1]);
            v0.z = lo32(acc[mp][2]); v0.w = lo32(acc[mp][3]);
            v1.x = lo32(acc[mp][4]); v1.y = lo32(acc[mp][5]);
            v1.z = lo32(acc[mp][6]); v1.w = lo32(acc[mp][7]);
        } else {
            v0.x = hi32(acc[mp][0]); v0.y = hi32(acc[mp][1]);
            v0.z = hi32(acc[mp][2]); v0.w = hi32(acc[mp][3]);
            v1.x = hi32(acc[mp][4]); v1.y = hi32(acc[mp][5]);
            v1.z = hi32(acc[mp][6]); v1.w = hi32(acc[mp][7]);
        }
        float* cp = C + (size_t)(m0 + tm * 8 + i) * N + n0 + tn * 8;
        *(float4*)cp = v0;
        *(float4*)(cp + 4) = v1;
    }
}

// ---------------- GEMM 128x64 (head, N=64) ----------------
#define AS_STR 132
#define BS_STR 68
__global__ void __launch_bounds__(256) gemm_nt(const float* __restrict__ A,
                                               const float* __restrict__ Bm,
                                               float* __restrict__ C, int N) {
    __shared__ __align__(16) float As[2][16 * AS_STR];
    __shared__ __align__(16) float Bs[2][16 * BS_STR];
    int tid = threadIdx.x;
    int m0 = blockIdx.y * 128, n0 = blockIdx.x * 64;
    int tm = tid & 15, tn = tid >> 4;
    const float* Ag = A + (size_t)m0 * 256;
    const float* Bg = Bm + (size_t)n0 * 256;
    int bn = tid >> 2, bkq = tid & 3;
    float4 ar[2], br;
#pragma unroll
    for (int j = 0; j < 2; j++) {
        int f = tid + j * 256;
        ar[j] = *(const float4*)(Ag + (size_t)(f >> 2) * 256 + (f & 3) * 4);
    }
    br = *(const float4*)(Bg + (size_t)bn * 256 + bkq * 4);
#pragma unroll
    for (int j = 0; j < 2; j++) {
        int f = tid + j * 256; int m = f >> 2, kq = f & 3;
        As[0][(kq * 4 + 0) * AS_STR + m] = ar[j].x;
        As[0][(kq * 4 + 1) * AS_STR + m] = ar[j].y;
        As[0][(kq * 4 + 2) * AS_STR + m] = ar[j].z;
        As[0][(kq * 4 + 3) * AS_STR + m] = ar[j].w;
    }
    Bs[0][(bkq * 4 + 0) * BS_STR + bn] = br.x;
    Bs[0][(bkq * 4 + 1) * BS_STR + bn] = br.y;
    Bs[0][(bkq * 4 + 2) * BS_STR + bn] = br.z;
    Bs[0][(bkq * 4 + 3) * BS_STR + bn] = br.w;
    __syncthreads();

    ull acc[4][4];
#pragma unroll
    for (int i = 0; i < 4; i++)
#pragma unroll
        for (int j = 0; j < 4; j++) acc[i][j] = 0ull;

    for (int c = 0; c < 16; c++) {
        int cur = c & 1;
        if (c < 15) {
#pragma unroll
            for (int j = 0; j < 2; j++) {
                int f = tid + j * 256;
                ar[j] = *(const float4*)(Ag + (size_t)(f >> 2) * 256 + (c + 1) * 16 + (f & 3) * 4);
            }
            br = *(const float4*)(Bg + (size_t)bn * 256 + (c + 1) * 16 + bkq * 4);
        }
#pragma unroll
        for (int k = 0; k < 16; k++) {
            ulonglong2 a01 = *(const ulonglong2*)&As[cur][k * AS_STR + tm * 8];
            ulonglong2 a23 = *(const ulonglong2*)&As[cur][k * AS_STR + tm * 8 + 4];
            float4 bq = *(const float4*)&Bs[cur][k * BS_STR + tn * 4];
            ull b0 = dup2(bq.x), b1 = dup2(bq.y), b2 = dup2(bq.z), b3 = dup2(bq.w);
            acc[0][0] = ffma2(a01.x, b0, acc[0][0]);
            acc[0][1] = ffma2(a01.x, b1, acc[0][1]);
            acc[0][2] = ffma2(a01.x, b2, acc[0][2]);
            acc[0][3] = ffma2(a01.x, b3, acc[0][3]);
            acc[1][0] = ffma2(a01.y, b0, acc[1][0]);
            acc[1][1] = ffma2(a01.y, b1, acc[1][1]);
            acc[1][2] = ffma2(a01.y, b2, acc[1][2]);
            acc[1][3] = ffma2(a01.y, b3, acc[1][3]);
            acc[2][0] = ffma2(a23.x, b0, acc[2][0]);
            acc[2][1] = ffma2(a23.x, b1, acc[2][1]);
            acc[2][2] = ffma2(a23.x, b2, acc[2][2]);
            acc[2][3] = ffma2(a23.x, b3, acc[2][3]);
            acc[3][0] = ffma2(a23.y, b0, acc[3][0]);
            acc[3][1] = ffma2(a23.y, b1, acc[3][1]);
            acc[3][2] = ffma2(a23.y, b2, acc[3][2]);
            acc[3][3] = ffma2(a23.y, b3, acc[3][3]);
        }
        if (c < 15) {
            int nxt = cur ^ 1;
#pragma unroll
            for (int j = 0; j < 2; j++) {
                int f = tid + j * 256; int m = f >> 2, kq = f & 3;
                As[nxt][(kq * 4 + 0) * AS_STR + m] = ar[j].x;
                As[nxt][(kq * 4 + 1) * AS_STR + m] = ar[j].y;
                As[nxt][(kq * 4 + 2) * AS_STR + m] = ar[j].z;
                As[nxt][(kq * 4 + 3) * AS_STR + m] = ar[j].w;
            }
            Bs[nxt][(bkq * 4 + 0) * BS_STR + bn] = br.x;
            Bs[nxt][(bkq * 4 + 1) * BS_STR + bn] = br.y;
            Bs[nxt][(bkq * 4 + 2) * BS_STR + bn] = br.z;
            Bs[nxt][(bkq * 4 + 3) * BS_STR + bn] = br.w;
            __syncthreads();
        }
    }
#pragma unroll
    for (int i = 0; i < 8; i++) {
        int mp = i >> 1;
        float4 v;
        if ((i & 1) == 0) {
            v.x = lo32(acc[mp][0]); v.y = lo32(acc[mp][1]);
            v.z = lo32(acc[mp][2]); v.w = lo32(acc[mp][3]);
        } else {
            v.x = hi32(acc[mp][0]); v.y = hi32(acc[mp][1]);
            v.z = hi32(acc[mp][2]); v.w = hi32(acc[mp][3]);
        }
        *(float4*)(C + (size_t)(m0 + tm * 8 + i) * N + n0 + tn * 4) = v;
    }
}

// ---------------- GRU recurrence: R12 best (byte-identical) ----------
#define CL_ 8
#define RW_ 8
#define HB_OFF   0
#define PART_OFF 4096
#define IDS_OFF  10240
#define MBAR_OFF 14336
#define SMEM_RECUR ((MBAR_OFF + 4) * 4)

__global__ void __launch_bounds__(256, 1) __cluster_dims__(CL_, 1, 1)
gru_recur(const float* __restrict__ whh, const float* __restrict__ bhh_g,
          const float* __restrict__ bih_g, const float* __restrict__ xgsrc,
          const int* __restrict__ ids_g, const float* __restrict__ embp,
          float* __restrict__ hout, int layer) {
    extern __shared__ __align__(16) float sm[];
    float* hb = sm + HB_OFF;
    float* part = sm + PART_OFF;
    int* ids_s = (int*)(sm + IDS_OFF);
    unsigned mbar_a = smem_u32(sm + MBAR_OFF);

    int tid = threadIdx.x;
    unsigned rank;
    asm("mov.u32 %0, %%cluster_ctarank;" : "=r"(rank));
    int cid = blockIdx.x >> 3;
    int d0 = rank * 32;
    int brow0 = cid * RW_;
    int w = tid >> 5, l = tid & 31;

    ull wreg[3][16];
#pragma unroll
    for (int g = 0; g < 3; g++) {
        const float* wrow = whh + (size_t)(g * 256 + d0 + l) * 256 + w * 32;
#pragma unroll
        for (int kp = 0; kp < 16; kp++)
            wreg[g][kp] = *(const ull*)(wrow + 2 * kp);
    }

    for (int i = tid; i < 2 * RW_ * 256; i += 256) hb[i] = 0.f;
    if (layer == 0)
        for (int i = tid; i < RW_ * T_; i += 256) ids_s[i] = ids_g[brow0 * T_ + i];
    if (tid == 0)
        asm volatile("mbarrier.init.shared::cta.b64 [%0], 8;" :: "r"(mbar_a) : "memory");

    int erw = w, edj = l;
    int dfull = d0 + edj;
    float bhr = bhh_g[dfull], bhz = bhh_g[256 + dfull], bhn = bhh_g[512 + dfull];
    float bir = bih_g[dfull], biz = bih_g[256 + dfull], bin_ = bih_g[512 + dfull];

    unsigned hb_local = smem_u32(hb);
    unsigned peer_hb[CL_], peer_mb[CL_];
#pragma unroll
    for (int r = 0; r < CL_; r++) {
        asm("mapa.shared::cluster.u32 %0, %1, %2;" : "=r"(peer_hb[r]) : "r"(hb_local), "r"(r));
        asm("mapa.shared::cluster.u32 %0, %1, %2;" : "=r"(peer_mb[r]) : "r"(mbar_a), "r"(r));
    }
    int pr = (l < 7) ? (l + (l >= (int)rank ? 1 : 0)) : 0;
    unsigned my_peer_hb = peer_hb[pr], my_peer_mb = peer_mb[pr];

    __syncthreads();
    cluster_sync_();

    for (int t = 0; t < T_; t++) {
        int p = t & 1;
        float* hcur = hb + p * 2048;

        float xr, xz, xn;
        if (layer == 0) {
            int id = ids_s[erw * T_ + t];
            const float* e = embp + (size_t)id * G_ + dfull;
            xr = __ldg(e); xz = __ldg(e + 256); xn = __ldg(e + 512);
        } else {
            const float* e = xgsrc + ((size_t)(brow0 + erw) * T_ + t) * G_ + dfull;
            xr = __ldg(e); xz = __ldg(e + 256); xn = __ldg(e + 512);
        }

        ull acc0[8], acc1[8], acc2_[8];
#pragma unroll
        for (int r = 0; r < 8; r++) { acc0[r] = 0ull; acc1[r] = 0ull; acc2_[r] = 0ull; }
        const float* hblk = hcur + w * 256;
#pragma unroll
        for (int it = 0; it < 8; it++) {
            ulonglong2 h4[8];
#pragma unroll
            for (int r = 0; r < 8; r++)
                h4[r] = *(const ulonglong2*)(hblk + r * 32 + (it << 2));
#pragma unroll
            for (int s = 0; s < 2; s++) {
                ull w0 = wreg[0][2 * it + s];
                ull w1 = wreg[1][2 * it + s];
                ull w2v = wreg[2][2 * it + s];
#pragma unroll
                for (int r = 0; r < 8; r++) {
                    ull hh = s ? h4[r].y : h4[r].x;
                    acc0[r] = ffma2(w0, hh, acc0[r]);
                    acc1[r] = ffma2(w1, hh, acc1[r]);
                    acc2_[r] = ffma2(w2v, hh, acc2_[r]);
                }
            }
        }
#pragma unroll
        for (int r = 0; r < 8; r++) {
            part[w * 768 + r * 96 + l]      = lo32(acc0[r]) + hi32(acc0[r]);
            part[w * 768 + r * 96 + 32 + l] = lo32(acc1[r]) + hi32(acc1[r]);
            part[w * 768 + r * 96 + 64 + l] = lo32(acc2_[r]) + hi32(acc2_[r]);
        }
        __syncthreads();

        float rs = 0.f, zs = 0.f, ns = 0.f;
#pragma unroll
        for (int kg = 0; kg < 8; kg++) {
            const float* pp = part + kg * 768 + erw * 96 + edj;
            rs += pp[0]; zs += pp[32]; ns += pp[64];
        }
        float hprev = hcur[rank * 256 + erw * 32 + edj];
        float rr = 0.5f + 0.5f * tanhapx(0.5f * (xr + bir + rs + bhr));
        float zz = 0.5f + 0.5f * tanhapx(0.5f * (xz + biz + zs + bhz));
        float nn = tanhapx(xn + bin_ + rr * (ns + bhn));
        float hn = (1.f - zz) * nn + zz * hprev;

        hout[((size_t)(brow0 + erw) * T_ + t) * 256 + dfull] = hn;
        unsigned row_off = (unsigned)((((p ^ 1) * 2048) + rank * 256 + erw * 32) * 4);
        hb[((p ^ 1) * 2048) + rank * 256 + erw * 32 + edj] = hn;
        __syncwarp();
        if (l < 7) {
            asm volatile("fence.proxy.async.shared::cta;" ::: "memory");
            asm volatile("cp.async.bulk.shared::cluster.shared::cta.mbarrier::complete_tx::bytes [%0], [%1], %2, [%3];"
                         :: "r"(my_peer_hb + row_off), "r"(hb_local + row_off), "r"(128), "r"(my_peer_mb) : "memory");
        }
        if (l == 0) {
            if (w == 0)
                asm volatile("mbarrier.arrive.expect_tx.shared::cta.b64 _, [%0], %1;"
                             :: "r"(mbar_a), "r"(7168) : "memory");
            else
                asm volatile("mbarrier.arrive.shared::cta.b64 _, [%0];"
                             :: "r"(mbar_a) : "memory");
        }
        asm volatile("{\n\t.reg .pred P;\n\tWL_%=:\n\tmbarrier.try_wait.parity.acquire.cta.shared::cta.b64 P, [%0], %1;\n\t@!P bra WL_%=;\n\t}\n"
                     :: "r"(mbar_a), "r"(p) : "memory");
    }
    cluster_sync_();
}

// ---------------- masked cross-entropy loss ----------------
__global__ void __launch_bounds__(256) loss_partial_kernel(const float* __restrict__ logits,
                                                           const int* __restrict__ targets,
                                                           const void* __restrict__ maskp,
                                                           float2* __restrict__ partials) {
    __shared__ float s1[256], s2[256];
    int tid = threadIdx.x;
    int i = blockIdx.x * 256 + tid;
    const float* lg = logits + (size_t)i * NS_;
    float mx = -1e30f;
#pragma unroll 8
    for (int j = 0; j < NS_; j++) mx = fmaxf(mx, lg[j]);
    float s = 0.f;
#pragma unroll 8
    for (int j = 0; j < NS_; j++) s += expf(lg[j] - mx);
    float nll = mx + logf(s) - lg[targets[i]];
    float m;
    int mode = g_mask_mode;
    if (mode == 0)      m = (float)((const int*)maskp)[i];
    else if (mode == 1) m = ((const float*)maskp)[i];
    else                m = (float)((const unsigned char*)maskp)[i];
    s1[tid] = nll * m;
    s2[tid] = m;
    __syncthreads();
    for (int o = 128; o; o >>= 1) {
        if (tid < o) { s1[tid] += s1[tid + o]; s2[tid] += s2[tid + o]; }
        __syncthreads();
    }
    if (tid == 0) partials[blockIdx.x] = make_float2(s1[0], s2[0]);
}

__global__ void __launch_bounds__(256) loss_final_kernel(const float2* __restrict__ partials,
                                                         float* __restrict__ out, int out_size) {
    __shared__ float s1[256], s2[256];
    int tid = threadIdx.x;
    float2 v = partials[tid];
    s1[tid] = v.x; s2[tid] = v.y;
    __syncthreads();
    for (int o = 128; o; o >>= 1) {
        if (tid < o) { s1[tid] += s1[tid + o]; s2[tid] += s2[tid + o]; }
        __syncthreads();
    }
    float msum = s2[0];
    float loss = (msum > 0.f) ? s1[0] / fmaxf(msum, 1.f) : 0.f;
    int start = (out_size >= BTN_) ? BTN_ : 0;
    for (int i = start + tid; i < out_size; i += 256) out[i] = loss;
}

// ---------------- launcher ----------------
extern "C" void kernel_launch(void* const* d_in, const int* in_sizes, int n_in,
                              void* d_out, int out_size) {
    const int* ids = (const int*)d_in[0];
    const int* tgt = (const int*)d_in[1];
    const void* mask = d_in[2];
    const float* emb = (const float*)d_in[3];
    const float* wih = (const float*)d_in[4];
    const float* whh = (const float*)d_in[5];
    const float* bih = (const float*)d_in[6];
    const float* bhh = (const float*)d_in[7];
    const float* hw  = (const float*)d_in[8];
    float* out = (float*)d_out;

    float *embp, *xg2, *h1, *h2; float2* lpart;
    ushort_ *h1hi, *h1lo, *wihhi, *wihlo;
    cudaGetSymbolAddress((void**)&embp, d_emb_proj);
    cudaGetSymbolAddress((void**)&xg2, d_xg2);
    cudaGetSymbolAddress((void**)&h1, d_h1);
    cudaGetSymbolAddress((void**)&h2, d_h2);
    cudaGetSymbolAddress((void**)&h1hi, d_h1hi);
    cudaGetSymbolAddress((void**)&h1lo, d_h1lo);
    cudaGetSymbolAddress((void**)&wihhi, d_wihhi);
    cudaGetSymbolAddress((void**)&wihlo, d_wihlo);
    cudaGetSymbolAddress((void**)&lpart, d_lpart);

    cudaFuncSetAttribute(gru_recur, cudaFuncAttributeMaxDynamicSharedMemorySize, SMEM_RECUR);
    cudaFuncSetAttribute(gemm_bfs, cudaFuncAttributeMaxDynamicSharedMemorySize, BFS_SMEM);

    probe_mask_kernel<<<1, 32>>>((const unsigned char*)mask);
    gemm128<<<dim3(6, 4), 256>>>(emb, wih, embp, G_);
    cvt_split<<<(G_ * 256 / 4 + 255) / 256, 256>>>(wih + 768 * 256, wihhi, wihlo, G_ * 256 / 4);
    gru_recur<<<128, 256, SMEM_RECUR>>>(whh, bhh, bih, (const float*)0, ids, embp, h1, 0);
    cvt_split<<<(M_ * 64 + 255) / 256, 256>>>(h1, h1hi, h1lo, M_ * 64);
    gemm_bfs<<<dim3(6, 512), 256, BFS_SMEM>>>(h1hi, h1lo, wihhi, wihlo, xg2, G_);
    gru_recur<<<128, 256, SMEM_RECUR>>>(whh + 768 * 256, bhh + 768, bih + 768, xg2, ids, embp, h2, 1);
    float* ldst = (out_size >= BTN_) ? out : xg2;
    gemm_nt<<<dim3(1, 512), 256>>>(h2, hw, ldst, NS_);
    loss_partial_kernel<<<256, 256>>>(ldst, tgt, mask, lpart);
    loss_final_kernel<<<1, 256>>>(lpart, out, out_size);
}

// round 15
// speedup vs baseline: 1.0182x; 1.0182x over previous
#include <cuda_runtime.h>
#include <cuda_bf16.h>
#include <cstdint>

#define B_  128
#define T_  512
#define G_  768
#define NS_ 64
#define M_  (B_*T_)
#define BTN_ (M_*NS_)
typedef unsigned long long ull;
typedef unsigned int uint32;
typedef unsigned short ushort_;

__device__ float d_emb_proj[512 * G_];
__device__ float d_xg2[(size_t)M_ * G_];
__device__ float d_h1[(size_t)M_ * 256];
__device__ float d_h2[(size_t)M_ * 256];
__device__ ushort_ d_wihhi[G_ * 256];
__device__ ushort_ d_wihlo[G_ * 256];
__device__ float2 d_lpart[256];
__device__ int g_mask_mode;

__device__ __forceinline__ ull ffma2(ull a, ull b, ull c) {
    ull d; asm("fma.rn.f32x2 %0, %1, %2, %3;" : "=l"(d) : "l"(a), "l"(b), "l"(c)); return d;
}
__device__ __forceinline__ ull dup2(float x) {
    ull d; asm("mov.b64 %0, {%1, %2};" : "=l"(d) : "f"(x), "f"(x)); return d;
}
__device__ __forceinline__ float lo32(ull v) { return __uint_as_float((unsigned)v); }
__device__ __forceinline__ float hi32(ull v) { return __uint_as_float((unsigned)(v >> 32)); }
__device__ __forceinline__ void cluster_sync_() {
    asm volatile("barrier.cluster.arrive.aligned;\n\tbarrier.cluster.wait.aligned;" ::: "memory");
}
__device__ __forceinline__ unsigned smem_u32(const void* p) {
    return (unsigned)__cvta_generic_to_shared(p);
}
__device__ __forceinline__ float tanhapx(float x) {
    float y; asm("tanh.approx.f32 %0, %1;" : "=f"(y) : "f"(x)); return y;
}

#define MMA16816(c, a0, a1, a2, a3, b0, b1) \
    asm volatile("mma.sync.aligned.m16n8k16.row.col.f32.bf16.bf16.f32 " \
                 "{%0,%1,%2,%3}, {%4,%5,%6,%7}, {%8,%9}, {%0,%1,%2,%3};" \
                 : "+f"((c)[0]), "+f"((c)[1]), "+f"((c)[2]), "+f"((c)[3]) \
                 : "r"(a0), "r"(a1), "r"(a2), "r"(a3), "r"(b0), "r"(b1))

__global__ void probe_mask_kernel(const unsigned char* __restrict__ m) {
    if (threadIdx.x == 0) {
        bool hasBig = false, offMult = false;
        for (int i = 0; i < 256; i++) {
            unsigned char c = m[i];
            if (c > 1) hasBig = true;
            if (c == 1 && (i & 3)) offMult = true;
        }
        g_mask_mode = hasBig ? 1 : (offMult ? 2 : 0);
    }
}

// ---------------- fp32 -> bf16 hi/lo split (weights only) ----------------
__global__ void __launch_bounds__(256) cvt_split(const float* __restrict__ src,
                                                 ushort_* __restrict__ hi,
                                                 ushort_* __restrict__ lo, int n4) {
    int i = blockIdx.x * 256 + threadIdx.x;
    if (i >= n4) return;
    float4 v = *(const float4*)(src + (size_t)i * 4);
    ushort_ h[4], l[4];
    float f[4] = {v.x, v.y, v.z, v.w};
#pragma unroll
    for (int j = 0; j < 4; j++) {
        __nv_bfloat16 hb = __float2bfloat16_rn(f[j]);
        h[j] = __bfloat16_as_ushort(hb);
        l[j] = __bfloat16_as_ushort(__float2bfloat16_rn(f[j] - __bfloat162float(hb)));
    }
    *(uint2*)(hi + (size_t)i * 4) = make_uint2((uint32)h[0] | ((uint32)h[1] << 16),
                                               (uint32)h[2] | ((uint32)h[3] << 16));
    *(uint2*)(lo + (size_t)i * 4) = make_uint2((uint32)l[0] | ((uint32)l[1] << 16),
                                               (uint32)l[2] | ((uint32)l[3] << 16));
}

// ---------------- split-bf16 TC GEMM: A fp32 (in-kernel split), B preconverted -
#define BST 12
#define MATW (128 * BST)
#define BFS_SMEM (8 * MATW * 4)

__device__ __forceinline__ void cvt_hl(float x, unsigned short& h, unsigned short& l) {
    __nv_bfloat16 hb = __float2bfloat16_rn(x);
    h = __bfloat16_as_ushort(hb);
    l = __bfloat16_as_ushort(__float2bfloat16_rn(x - __bfloat162float(hb)));
}

__global__ void __launch_bounds__(256) gemm_bfs(const float* __restrict__ A,
                                                const ushort_* __restrict__ Bhi,
                                                const ushort_* __restrict__ Blo,
                                                float* __restrict__ C, int N) {
    extern __shared__ __align__(16) uint32 bsm[];
    uint32* Ah = bsm;
    uint32* Al = bsm + 2 * MATW;
    uint32* Bh = bsm + 4 * MATW;
    uint32* Bl = bsm + 6 * MATW;

    int tid = threadIdx.x;
    int m0 = blockIdx.y * 128, n0 = blockIdx.x * 128;
    int wid = tid >> 5, l = tid & 31;
    int wm = wid & 3, wn = wid >> 2;
    const float* Ag = A + (size_t)m0 * 256;
    const ushort_* Bhg = Bhi + (size_t)n0 * 256;
    const ushort_* Blg = Blo + (size_t)n0 * 256;

    float c[16][4];
#pragma unroll
    for (int i = 0; i < 16; i++)
#pragma unroll
        for (int j = 0; j < 4; j++) c[i][j] = 0.f;

    // loaders: A as R13 (fp32 + split), B direct from preconverted arrays
    int lrow = tid >> 1, lhalf = tid & 1;
    size_t bsrc = (size_t)lrow * 256 + lhalf * 8;
    int bdst = lrow * BST + lhalf * 4;

    float4 av[2];
    uint4 vbh, vbl;
#pragma unroll
    for (int j = 0; j < 2; j++) {
        int f = tid + j * 256; int row = f >> 2, q = f & 3;
        av[j] = *(const float4*)(Ag + (size_t)row * 256 + q * 4);
    }
    vbh = *(const uint4*)(Bhg + bsrc);
    vbl = *(const uint4*)(Blg + bsrc);
#pragma unroll
    for (int j = 0; j < 2; j++) {
        int f = tid + j * 256; int row = f >> 2, q = f & 3;
        unsigned short h0, h1, h2, h3, l0, l1, l2, l3;
        cvt_hl(av[j].x, h0, l0); cvt_hl(av[j].y, h1, l1);
        cvt_hl(av[j].z, h2, l2); cvt_hl(av[j].w, h3, l3);
        Ah[row * BST + q * 2]     = (uint32)h0 | ((uint32)h1 << 16);
        Ah[row * BST + q * 2 + 1] = (uint32)h2 | ((uint32)h3 << 16);
        Al[row * BST + q * 2]     = (uint32)l0 | ((uint32)l1 << 16);
        Al[row * BST + q * 2 + 1] = (uint32)l2 | ((uint32)l3 << 16);
    }
    *(uint4*)&Bh[bdst] = vbh;
    *(uint4*)&Bl[bdst] = vbl;
    __syncthreads();

    int fr = l >> 2, kp = l & 3;
    for (int ch = 0; ch < 16; ch++) {
        int cur = ch & 1;
        uint32* Ahc = Ah + cur * MATW;
        uint32* Alc = Al + cur * MATW;
        uint32* Bhc = Bh + cur * MATW;
        uint32* Blc = Bl + cur * MATW;
        if (ch < 15) {
#pragma unroll
            for (int j = 0; j < 2; j++) {
                int f = tid + j * 256; int row = f >> 2, q = f & 3;
                av[j] = *(const float4*)(Ag + (size_t)row * 256 + (ch + 1) * 16 + q * 4);
            }
            vbh = *(const uint4*)(Bhg + bsrc + (ch + 1) * 16);
            vbl = *(const uint4*)(Blg + bsrc + (ch + 1) * 16);
        }
        uint32 ah[2][4], al_[2][4];
#pragma unroll
        for (int mi = 0; mi < 2; mi++) {
            int r = wm * 32 + mi * 16 + fr;
            ah[mi][0] = Ahc[r * BST + kp];
            ah[mi][1] = Ahc[(r + 8) * BST + kp];
            ah[mi][2] = Ahc[r * BST + 4 + kp];
            ah[mi][3] = Ahc[(r + 8) * BST + 4 + kp];
            al_[mi][0] = Alc[r * BST + kp];
            al_[mi][1] = Alc[(r + 8) * BST + kp];
            al_[mi][2] = Alc[r * BST + 4 + kp];
            al_[mi][3] = Alc[(r + 8) * BST + 4 + kp];
        }
#pragma unroll
        for (int ni = 0; ni < 8; ni++) {
            int nr = wn * 64 + ni * 8 + fr;
            uint32 bh0 = Bhc[nr * BST + kp];
            uint32 bh1 = Bhc[nr * BST + 4 + kp];
            uint32 bl0 = Blc[nr * BST + kp];
            uint32 bl1 = Blc[nr * BST + 4 + kp];
#pragma unroll
            for (int mi = 0; mi < 2; mi++) {
                MMA16816(c[mi * 8 + ni], ah[mi][0], ah[mi][1], ah[mi][2], ah[mi][3], bh0, bh1);
                MMA16816(c[mi * 8 + ni], ah[mi][0], ah[mi][1], ah[mi][2], ah[mi][3], bl0, bl1);
                MMA16816(c[mi * 8 + ni], al_[mi][0], al_[mi][1], al_[mi][2], al_[mi][3], bh0, bh1);
            }
        }
        if (ch < 15) {
            int nxt = cur ^ 1;
            uint32* Ahn = Ah + nxt * MATW;
            uint32* Aln = Al + nxt * MATW;
#pragma unroll
            for (int j = 0; j < 2; j++) {
                int f = tid + j * 256; int row = f >> 2, q = f & 3;
                unsigned short h0, h1, h2, h3, l0, l1, l2, l3;
                cvt_hl(av[j].x, h0, l0); cvt_hl(av[j].y, h1, l1);
                cvt_hl(av[j].z, h2, l2); cvt_hl(av[j].w, h3, l3);
                Ahn[row * BST + q * 2]     = (uint32)h0 | ((uint32)h1 << 16);
                Ahn[row * BST + q * 2 + 1] = (uint32)h2 | ((uint32)h3 << 16);
                Aln[row * BST + q * 2]     = (uint32)l0 | ((uint32)l1 << 16);
                Aln[row * BST + q * 2 + 1] = (uint32)l2 | ((uint32)l3 << 16);
            }
            *(uint4*)&Bh[nxt * MATW + bdst] = vbh;
            *(uint4*)&Bl[nxt * MATW + bdst] = vbl;
            __syncthreads();
        }
    }
#pragma unroll
    for (int mi = 0; mi < 2; mi++)
#pragma unroll
        for (int ni = 0; ni < 8; ni++) {
            int row = m0 + wm * 32 + mi * 16 + fr;
            int col = n0 + wn * 64 + ni * 8 + kp * 2;
            float2* p0 = (float2*)(C + (size_t)row * N + col);
            float2* p1 = (float2*)(C + (size_t)(row + 8) * N + col);
            *p0 = make_float2(c[mi * 8 + ni][0], c[mi * 8 + ni][1]);
            *p1 = make_float2(c[mi * 8 + ni][2], c[mi * 8 + ni][3]);
        }
}

// ---------------- GEMM 128x128 fp32 (emb-proj only) ----------------
#define GS 132
__global__ void __launch_bounds__(256) gemm128(const float* __restrict__ A,
                                               const float* __restrict__ Bm,
                                               float* __restrict__ C, int N) {
    __shared__ __align__(16) float As[2][16 * GS];
    __shared__ __align__(16) float Bs[2][16 * GS];
    int tid = threadIdx.x;
    int m0 = blockIdx.y * 128, n0 = blockIdx.x * 128;
    int tm = tid & 15, tn = tid >> 4;
    const float* Ag = A + (size_t)m0 * 256;
    const float* Bg = Bm + (size_t)n0 * 256;

    float4 ar[2], br[2];
#pragma unroll
    for (int j = 0; j < 2; j++) {
        int f = tid + j * 256;
        ar[j] = *(const float4*)(Ag + (size_t)(f >> 2) * 256 + (f & 3) * 4);
        br[j] = *(const float4*)(Bg + (size_t)(f >> 2) * 256 + (f & 3) * 4);
    }
#pragma unroll
    for (int j = 0; j < 2; j++) {
        int f = tid + j * 256; int row = f >> 2, kq = f & 3;
        As[0][(kq * 4 + 0) * GS + row] = ar[j].x;
        As[0][(kq * 4 + 1) * GS + row] = ar[j].y;
        As[0][(kq * 4 + 2) * GS + row] = ar[j].z;
        As[0][(kq * 4 + 3) * GS + row] = ar[j].w;
        Bs[0][(kq * 4 + 0) * GS + row] = br[j].x;
        Bs[0][(kq * 4 + 1) * GS + row] = br[j].y;
        Bs[0][(kq * 4 + 2) * GS + row] = br[j].z;
        Bs[0][(kq * 4 + 3) * GS + row] = br[j].w;
    }
    __syncthreads();

    ull acc[4][8];
#pragma unroll
    for (int i = 0; i < 4; i++)
#pragma unroll
        for (int j = 0; j < 8; j++) acc[i][j] = 0ull;

    for (int ch = 0; ch < 16; ch++) {
        int cur = ch & 1;
        if (ch < 15) {
#pragma unroll
            for (int j = 0; j < 2; j++) {
                int f = tid + j * 256;
                ar[j] = *(const float4*)(Ag + (size_t)(f >> 2) * 256 + (ch + 1) * 16 + (f & 3) * 4);
                br[j] = *(const float4*)(Bg + (size_t)(f >> 2) * 256 + (ch + 1) * 16 + (f & 3) * 4);
            }
        }
#pragma unroll
        for (int k = 0; k < 16; k++) {
            ulonglong2 a01 = *(const ulonglong2*)&As[cur][k * GS + tm * 8];
            ulonglong2 a23 = *(const ulonglong2*)&As[cur][k * GS + tm * 8 + 4];
            float4 bq0 = *(const float4*)&Bs[cur][k * GS + tn * 8];
            float4 bq1 = *(const float4*)&Bs[cur][k * GS + tn * 8 + 4];
            float bf[8] = {bq0.x, bq0.y, bq0.z, bq0.w, bq1.x, bq1.y, bq1.z, bq1.w};
#pragma unroll
            for (int j = 0; j < 8; j++) {
                ull bb = dup2(bf[j]);
                acc[0][j] = ffma2(a01.x, bb, acc[0][j]);
                acc[1][j] = ffma2(a01.y, bb, acc[1][j]);
                acc[2][j] = ffma2(a23.x, bb, acc[2][j]);
                acc[3][j] = ffma2(a23.y, bb, acc[3][j]);
            }
        }
        if (ch < 15) {
            int nxt = cur ^ 1;
#pragma unroll
            for (int j = 0; j < 2; j++) {
                int f = tid + j * 256; int row = f >> 2, kq = f & 3;
                As[nxt][(kq * 4 + 0) * GS + row] = ar[j].x;
                As[nxt][(kq * 4 + 1) * GS + row] = ar[j].y;
                As[nxt][(kq * 4 + 2) * GS + row] = ar[j].z;
                As[nxt][(kq * 4 + 3) * GS + row] = ar[j].w;
                Bs[nxt][(kq * 4 + 0) * GS + row] = br[j].x;
                Bs[nxt][(kq * 4 + 1) * GS + row] = br[j].y;
                Bs[nxt][(kq * 4 + 2) * GS + row] = br[j].z;
                Bs[nxt][(kq * 4 + 3) * GS + row] = br[j].w;
            }
            __syncthreads();
        }
    }
#pragma unroll
    for (int i = 0; i < 8; i++) {
        int mp = i >> 1;
        float4 v0, v1;
        if ((i & 1) == 0) {
            v0.x = lo32(acc[mp][0]); v0.y = lo32(acc[mp][1]);
            v0.z = lo32(acc[mp][2]); v0.w = lo32(acc[mp][3]);
            v1.x = lo32(acc[mp][4]); v1.y = lo32(acc[mp][5]);
            v1.z = lo32(acc[mp][6]); v1.w = lo32(acc[mp][7]);
        } else {
            v0.x = hi32(acc[mp][0]); v0.y = hi32(acc[mp][1]);
            v0.z = hi32(acc[mp][2]); v0.w = hi32(acc[mp][3]);
            v1.x = hi32(acc[mp][4]); v1.y = hi32(acc[mp][5]);
            v1.z = hi32(acc[mp][6]); v1.w = hi32(acc[mp][7]);
        }
        float* cp = C + (size_t)(m0 + tm * 8 + i) * N + n0 + tn * 8;
        *(float4*)cp = v0;
        *(float4*)(cp + 4) = v1;
    }
}

// ---------------- GEMM 128x64 (head, N=64) ----------------
#define AS_STR 132
#define BS_STR 68
__global__ void __launch_bounds__(256) gemm_nt(const float* __restrict__ A,
                                               const float* __restrict__ Bm,
                                               float* __restrict__ C, int N) {
    __shared__ __align__(16) float As[2][16 * AS_STR];
    __shared__ __align__(16) float Bs[2][16 * BS_STR];
    int tid = threadIdx.x;
    int m0 = blockIdx.y * 128, n0 = blockIdx.x * 64;
    int tm = tid & 15, tn = tid >> 4;
    const float* Ag = A + (size_t)m0 * 256;
    const float* Bg = Bm + (size_t)n0 * 256;
    int bn = tid >> 2, bkq = tid & 3;
    float4 ar[2], br;
#pragma unroll
    for (int j = 0; j < 2; j++) {
        int f = tid + j * 256;
        ar[j] = *(const float4*)(Ag + (size_t)(f >> 2) * 256 + (f & 3) * 4);
    }
    br = *(const float4*)(Bg + (size_t)bn * 256 + bkq * 4);
#pragma unroll
    for (int j = 0; j < 2; j++) {
        int f = tid + j * 256; int m = f >> 2, kq = f & 3;
        As[0][(kq * 4 + 0) * AS_STR + m] = ar[j].x;
        As[0][(kq * 4 + 1) * AS_STR + m] = ar[j].y;
        As[0][(kq * 4 + 2) * AS_STR + m] = ar[j].z;
        As[0][(kq * 4 + 3) * AS_STR + m] = ar[j].w;
    }
    Bs[0][(bkq * 4 + 0) * BS_STR + bn] = br.x;
    Bs[0][(bkq * 4 + 1) * BS_STR + bn] = br.y;
    Bs[0][(bkq * 4 + 2) * BS_STR + bn] = br.z;
    Bs[0][(bkq * 4 + 3) * BS_STR + bn] = br.w;
    __syncthreads();

    ull acc[4][4];
#pragma unroll
    for (int i = 0; i < 4; i++)
#pragma unroll
        for (int j = 0; j < 4; j++) acc[i][j] = 0ull;

    for (int c = 0; c < 16; c++) {
        int cur = c & 1;
        if (c < 15) {
#pragma unroll
            for (int j = 0; j < 2; j++) {
                int f = tid + j * 256;
                ar[j] = *(const float4*)(Ag + (size_t)(f >> 2) * 256 + (c + 1) * 16 + (f & 3) * 4);
            }
            br = *(const float4*)(Bg + (size_t)bn * 256 + (c + 1) * 16 + bkq * 4);
        }
#pragma unroll
        for (int k = 0; k < 16; k++) {
            ulonglong2 a01 = *(const ulonglong2*)&As[cur][k * AS_STR + tm * 8];
            ulonglong2 a23 = *(const ulonglong2*)&As[cur][k * AS_STR + tm * 8 + 4];
            float4 bq = *(const float4*)&Bs[cur][k * BS_STR + tn * 4];
            ull b0 = dup2(bq.x), b1 = dup2(bq.y), b2 = dup2(bq.z), b3 = dup2(bq.w);
            acc[0][0] = ffma2(a01.x, b0, acc[0][0]);
            acc[0][1] = ffma2(a01.x, b1, acc[0][1]);
            acc[0][2] = ffma2(a01.x, b2, acc[0][2]);
            acc[0][3] = ffma2(a01.x, b3, acc[0][3]);
            acc[1][0] = ffma2(a01.y, b0, acc[1][0]);
            acc[1][1] = ffma2(a01.y, b1, acc[1][1]);
            acc[1][2] = ffma2(a01.y, b2, acc[1][2]);
            acc[1][3] = ffma2(a01.y, b3, acc[1][3]);
            acc[2][0] = ffma2(a23.x, b0, acc[2][0]);
            acc[2][1] = ffma2(a23.x, b1, acc[2][1]);
            acc[2][2] = ffma2(a23.x, b2, acc[2][2]);
            acc[2][3] = ffma2(a23.x, b3, acc[2][3]);
            acc[3][0] = ffma2(a23.y, b0, acc[3][0]);
            acc[3][1] = ffma2(a23.y, b1, acc[3][1]);
            acc[3][2] = ffma2(a23.y, b2, acc[3][2]);
            acc[3][3] = ffma2(a23.y, b3, acc[3][3]);
        }
        if (c < 15) {
            int nxt = cur ^ 1;
#pragma unroll
            for (int j = 0; j < 2; j++) {
                int f = tid + j * 256; int m = f >> 2, kq = f & 3;
                As[nxt][(kq * 4 + 0) * AS_STR + m] = ar[j].x;
                As[nxt][(kq * 4 + 1) * AS_STR + m] = ar[j].y;
                As[nxt][(kq * 4 + 2) * AS_STR + m] = ar[j].z;
                As[nxt][(kq * 4 + 3) * AS_STR + m] = ar[j].w;
            }
            Bs[nxt][(bkq * 4 + 0) * BS_STR + bn] = br.x;
            Bs[nxt][(bkq * 4 + 1) * BS_STR + bn] = br.y;
            Bs[nxt][(bkq * 4 + 2) * BS_STR + bn] = br.z;
            Bs[nxt][(bkq * 4 + 3) * BS_STR + bn] = br.w;
            __syncthreads();
        }
    }
#pragma unroll
    for (int i = 0; i < 8; i++) {
        int mp = i >> 1;
        float4 v;
        if ((i & 1) == 0) {
            v.x = lo32(acc[mp][0]); v.y = lo32(acc[mp][1]);
            v.z = lo32(acc[mp][2]); v.w = lo32(acc[mp][3]);
        } else {
            v.x = hi32(acc[mp][0]); v.y = hi32(acc[mp][1]);
            v.z = hi32(acc[mp][2]); v.w = hi32(acc[mp][3]);
        }
        *(float4*)(C + (size_t)(m0 + tm * 8 + i) * N + n0 + tn * 4) = v;
    }
}

// ---------------- GRU recurrence: R12 best (byte-identical) ----------
#define CL_ 8
#define RW_ 8
#define HB_OFF   0
#define PART_OFF 4096
#define IDS_OFF  10240
#define MBAR_OFF 14336
#define SMEM_RECUR ((MBAR_OFF + 4) * 4)

__global__ void __launch_bounds__(256, 1) __cluster_dims__(CL_, 1, 1)
gru_recur(const float* __restrict__ whh, const float* __restrict__ bhh_g,
          const float* __restrict__ bih_g, const float* __restrict__ xgsrc,
          const int* __restrict__ ids_g, const float* __restrict__ embp,
          float* __restrict__ hout, int layer) {
    extern __shared__ __align__(16) float sm[];
    float* hb = sm + HB_OFF;
    float* part = sm + PART_OFF;
    int* ids_s = (int*)(sm + IDS_OFF);
    unsigned mbar_a = smem_u32(sm + MBAR_OFF);

    int tid = threadIdx.x;
    unsigned rank;
    asm("mov.u32 %0, %%cluster_ctarank;" : "=r"(rank));
    int cid = blockIdx.x >> 3;
    int d0 = rank * 32;
    int brow0 = cid * RW_;
    int w = tid >> 5, l = tid & 31;

    ull wreg[3][16];
#pragma unroll
    for (int g = 0; g < 3; g++) {
        const float* wrow = whh + (size_t)(g * 256 + d0 + l) * 256 + w * 32;
#pragma unroll
        for (int kp = 0; kp < 16; kp++)
            wreg[g][kp] = *(const ull*)(wrow + 2 * kp);
    }

    for (int i = tid; i < 2 * RW_ * 256; i += 256) hb[i] = 0.f;
    if (layer == 0)
        for (int i = tid; i < RW_ * T_; i += 256) ids_s[i] = ids_g[brow0 * T_ + i];
    if (tid == 0)
        asm volatile("mbarrier.init.shared::cta.b64 [%0], 8;" :: "r"(mbar_a) : "memory");

    int erw = w, edj = l;
    int dfull = d0 + edj;
    float bhr = bhh_g[dfull], bhz = bhh_g[256 + dfull], bhn = bhh_g[512 + dfull];
    float bir = bih_g[dfull], biz = bih_g[256 + dfull], bin_ = bih_g[512 + dfull];

    unsigned hb_local = smem_u32(hb);
    unsigned peer_hb[CL_], peer_mb[CL_];
#pragma unroll
    for (int r = 0; r < CL_; r++) {
        asm("mapa.shared::cluster.u32 %0, %1, %2;" : "=r"(peer_hb[r]) : "r"(hb_local), "r"(r));
        asm("mapa.shared::cluster.u32 %0, %1, %2;" : "=r"(peer_mb[r]) : "r"(mbar_a), "r"(r));
    }
    int pr = (l < 7) ? (l + (l >= (int)rank ? 1 : 0)) : 0;
    unsigned my_peer_hb = peer_hb[pr], my_peer_mb = peer_mb[pr];

    __syncthreads();
    cluster_sync_();

    for (int t = 0; t < T_; t++) {
        int p = t & 1;
        float* hcur = hb + p * 2048;

        float xr, xz, xn;
        if (layer == 0) {
            int id = ids_s[erw * T_ + t];
            const float* e = embp + (size_t)id * G_ + dfull;
            xr = __ldg(e); xz = __ldg(e + 256); xn = __ldg(e + 512);
        } else {
            const float* e = xgsrc + ((size_t)(brow0 + erw) * T_ + t) * G_ + dfull;
            xr = __ldg(e); xz = __ldg(e + 256); xn = __ldg(e + 512);
        }

        ull acc0[8], acc1[8], acc2_[8];
#pragma unroll
        for (int r = 0; r < 8; r++) { acc0[r] = 0ull; acc1[r] = 0ull; acc2_[r] = 0ull; }
        const float* hblk = hcur + w * 256;
#pragma unroll
        for (int it = 0; it < 8; it++) {
            ulonglong2 h4[8];
#pragma unroll
            for (int r = 0; r < 8; r++)
                h4[r] = *(const ulonglong2*)(hblk + r * 32 + (it << 2));
#pragma unroll
            for (int s = 0; s < 2; s++) {
                ull w0 = wreg[0][2 * it + s];
                ull w1 = wreg[1][2 * it + s];
                ull w2v = wreg[2][2 * it + s];
#pragma unroll
                for (int r = 0; r < 8; r++) {
                    ull hh = s ? h4[r].y : h4[r].x;
                    acc0[r] = ffma2(w0, hh, acc0[r]);
                    acc1[r] = ffma2(w1, hh, acc1[r]);
                    acc2_[r] = ffma2(w2v, hh, acc2_[r]);
                }
            }
        }
#pragma unroll
        for (int r = 0; r < 8; r++) {
            part[w * 768 + r * 96 + l]      = lo32(acc0[r]) + hi32(acc0[r]);
            part[w * 768 + r * 96 + 32 + l] = lo32(acc1[r]) + hi32(acc1[r]);
            part[w * 768 + r * 96 + 64 + l] = lo32(acc2_[r]) + hi32(acc2_[r]);
        }
        __syncthreads();

        float rs = 0.f, zs = 0.f, ns = 0.f;
#pragma unroll
        for (int kg = 0; kg < 8; kg++) {
            const float* pp = part + kg * 768 + erw * 96 + edj;
            rs += pp[0]; zs += pp[32]; ns += pp[64];
        }
        float hprev = hcur[rank * 256 + erw * 32 + edj];
        float rr = 0.5f + 0.5f * tanhapx(0.5f * (xr + bir + rs + bhr));
        float zz = 0.5f + 0.5f * tanhapx(0.5f * (xz + biz + zs + bhz));
        float nn = tanhapx(xn + bin_ + rr * (ns + bhn));
        float hn = (1.f - zz) * nn + zz * hprev;

        hout[((size_t)(brow0 + erw) * T_ + t) * 256 + dfull] = hn;
        unsigned row_off = (unsigned)((((p ^ 1) * 2048) + rank * 256 + erw * 32) * 4);
        hb[((p ^ 1) * 2048) + rank * 256 + erw * 32 + edj] = hn;
        __syncwarp();
        if (l < 7) {
            asm volatile("fence.proxy.async.shared::cta;" ::: "memory");
            asm volatile("cp.async.bulk.shared::cluster.shared::cta.mbarrier::complete_tx::bytes [%0], [%1], %2, [%3];"
                         :: "r"(my_peer_hb + row_off), "r"(hb_local + row_off), "r"(128), "r"(my_peer_mb) : "memory");
        }
        if (l == 0) {
            if (w == 0)
                asm volatile("mbarrier.arrive.expect_tx.shared::cta.b64 _, [%0], %1;"
                             :: "r"(mbar_a), "r"(7168) : "memory");
            else
                asm volatile("mbarrier.arrive.shared::cta.b64 _, [%0];"
                             :: "r"(mbar_a) : "memory");
        }
        asm volatile("{\n\t.reg .pred P;\n\tWL_%=:\n\tmbarrier.try_wait.parity.acquire.cta.shared::cta.b64 P, [%0], %1;\n\t@!P bra WL_%=;\n\t}\n"
                     :: "r"(mbar_a), "r"(p) : "memory");
    }
    cluster_sync_();
}

// ---------------- masked cross-entropy loss ----------------
__global__ void __launch_bounds__(256) loss_partial_kernel(const float* __restrict__ logits,
                                                           const int* __restrict__ targets,
                                                           const void* __restrict__ maskp,
                                                           float2* __restrict__ partials) {
    __shared__ float s1[256], s2[256];
    int tid = threadIdx.x;
    int i = blockIdx.x * 256 + tid;
    const float* lg = logits + (size_t)i * NS_;
    float mx = -1e30f;
#pragma unroll 8
    for (int j = 0; j < NS_; j++) mx = fmaxf(mx, lg[j]);
    float s = 0.f;
#pragma unroll 8
    for (int j = 0; j < NS_; j++) s += expf(lg[j] - mx);
    float nll = mx + logf(s) - lg[targets[i]];
    float m;
    int mode = g_mask_mode;
    if (mode == 0)      m = (float)((const int*)maskp)[i];
    else if (mode == 1) m = ((const float*)maskp)[i];
    else                m = (float)((const unsigned char*)maskp)[i];
    s1[tid] = nll * m;
    s2[tid] = m;
    __syncthreads();
    for (int o = 128; o; o >>= 1) {
        if (tid < o) { s1[tid] += s1[tid + o]; s2[tid] += s2[tid + o]; }
        __syncthreads();
    }
    if (tid == 0) partials[blockIdx.x] = make_float2(s1[0], s2[0]);
}

__global__ void __launch_bounds__(256) loss_final_kernel(const float2* __restrict__ partials,
                                                         float* __restrict__ out, int out_size) {
    __shared__ float s1[256], s2[256];
    int tid = threadIdx.x;
    float2 v = partials[tid];
    s1[tid] = v.x; s2[tid] = v.y;
    __syncthreads();
    for (int o = 128; o; o >>= 1) {
        if (tid < o) { s1[tid] += s1[tid + o]; s2[tid] += s2[tid + o]; }
        __syncthreads();
    }
    float msum = s2[0];
    float loss = (msum > 0.f) ? s1[0] / fmaxf(msum, 1.f) : 0.f;
    int start = (out_size >= BTN_) ? BTN_ : 0;
    for (int i = start + tid; i < out_size; i += 256) out[i] = loss;
}

// ---------------- launcher ----------------
extern "C" void kernel_launch(void* const* d_in, const int* in_sizes, int n_in,
                              void* d_out, int out_size) {
    const int* ids = (const int*)d_in[0];
    const int* tgt = (const int*)d_in[1];
    const void* mask = d_in[2];
    const float* emb = (const float*)d_in[3];
    const float* wih = (const float*)d_in[4];
    const float* whh = (const float*)d_in[5];
    const float* bih = (const float*)d_in[6];
    const float* bhh = (const float*)d_in[7];
    const float* hw  = (const float*)d_in[8];
    float* out = (float*)d_out;

    float *embp, *xg2, *h1, *h2; float2* lpart;
    ushort_ *wihhi, *wihlo;
    cudaGetSymbolAddress((void**)&embp, d_emb_proj);
    cudaGetSymbolAddress((void**)&xg2, d_xg2);
    cudaGetSymbolAddress((void**)&h1, d_h1);
    cudaGetSymbolAddress((void**)&h2, d_h2);
    cudaGetSymbolAddress((void**)&wihhi, d_wihhi);
    cudaGetSymbolAddress((void**)&wihlo, d_wihlo);
    cudaGetSymbolAddress((void**)&lpart, d_lpart);

    cudaFuncSetAttribute(gru_recur, cudaFuncAttributeMaxDynamicSharedMemorySize, SMEM_RECUR);
    cudaFuncSetAttribute(gemm_bfs, cudaFuncAttributeMaxDynamicSharedMemorySize, BFS_SMEM);

    probe_mask_kernel<<<1, 32>>>((const unsigned char*)mask);
    gemm128<<<dim3(6, 4), 256>>>(emb, wih, embp, G_);
    cvt_split<<<(G_ * 256 / 4 + 255) / 256, 256>>>(wih + 768 * 256, wihhi, wihlo, G_ * 256 / 4);
    gru_recur<<<128, 256, SMEM_RECUR>>>(whh, bhh, bih, (const float*)0, ids, embp, h1, 0);
    gemm_bfs<<<dim3(6, 512), 256, BFS_SMEM>>>(h1, wihhi, wihlo, xg2, G_);
    gru_recur<<<128, 256, SMEM_RECUR>>>(whh + 768 * 256, bhh + 768, bih + 768, xg2, ids, embp, h2, 1);
    float* ldst = (out_size >= BTN_) ? out : xg2;
    gemm_nt<<<dim3(1, 512), 256>>>(h2, hw, ldst, NS_);
    loss_partial_kernel<<<256, 256>>>(ldst, tgt, mask, lpart);
    loss_final_kernel<<<1, 256>>>(lpart, out, out_size);
}

// round 16
// speedup vs baseline: 1.0310x; 1.0126x over previous
#include <cuda_runtime.h>
#include <cuda_bf16.h>
#include <cstdint>

#define B_  128
#define T_  512
#define G_  768
#define NS_ 64
#define M_  (B_*T_)
#define BTN_ (M_*NS_)
typedef unsigned long long ull;
typedef unsigned int uint32;
typedef unsigned short ushort_;

__device__ float d_emb_proj[512 * G_];
__device__ float d_xg2[(size_t)M_ * G_];
__device__ float d_h1[(size_t)M_ * 256];
__device__ float d_h2[(size_t)M_ * 256];
__device__ ushort_ d_wihhi[G_ * 256];
__device__ ushort_ d_wihlo[G_ * 256];
__device__ ushort_ d_hwhi[NS_ * 256];
__device__ ushort_ d_hwlo[NS_ * 256];
__device__ float2 d_lpart[256];
__device__ int g_mask_mode;

__device__ __forceinline__ ull ffma2(ull a, ull b, ull c) {
    ull d; asm("fma.rn.f32x2 %0, %1, %2, %3;" : "=l"(d) : "l"(a), "l"(b), "l"(c)); return d;
}
__device__ __forceinline__ ull dup2(float x) {
    ull d; asm("mov.b64 %0, {%1, %2};" : "=l"(d) : "f"(x), "f"(x)); return d;
}
__device__ __forceinline__ float lo32(ull v) { return __uint_as_float((unsigned)v); }
__device__ __forceinline__ float hi32(ull v) { return __uint_as_float((unsigned)(v >> 32)); }
__device__ __forceinline__ void cluster_sync_() {
    asm volatile("barrier.cluster.arrive.aligned;\n\tbarrier.cluster.wait.aligned;" ::: "memory");
}
__device__ __forceinline__ unsigned smem_u32(const void* p) {
    return (unsigned)__cvta_generic_to_shared(p);
}
__device__ __forceinline__ float tanhapx(float x) {
    float y; asm("tanh.approx.f32 %0, %1;" : "=f"(y) : "f"(x)); return y;
}

#define MMA16816(c, a0, a1, a2, a3, b0, b1) \
    asm volatile("mma.sync.aligned.m16n8k16.row.col.f32.bf16.bf16.f32 " \
                 "{%0,%1,%2,%3}, {%4,%5,%6,%7}, {%8,%9}, {%0,%1,%2,%3};" \
                 : "+f"((c)[0]), "+f"((c)[1]), "+f"((c)[2]), "+f"((c)[3]) \
                 : "r"(a0), "r"(a1), "r"(a2), "r"(a3), "r"(b0), "r"(b1))

__global__ void probe_mask_kernel(const unsigned char* __restrict__ m) {
    if (threadIdx.x == 0) {
        bool hasBig = false, offMult = false;
        for (int i = 0; i < 256; i++) {
            unsigned char c = m[i];
            if (c > 1) hasBig = true;
            if (c == 1 && (i & 3)) offMult = true;
        }
        g_mask_mode = hasBig ? 1 : (offMult ? 2 : 0);
    }
}

// ---------------- fp32 -> bf16 hi/lo split ----------------
__global__ void __launch_bounds__(256) cvt_split(const float* __restrict__ src,
                                                 ushort_* __restrict__ hi,
                                                 ushort_* __restrict__ lo, int n4) {
    int i = blockIdx.x * 256 + threadIdx.x;
    if (i >= n4) return;
    float4 v = *(const float4*)(src + (size_t)i * 4);
    ushort_ h[4], l[4];
    float f[4] = {v.x, v.y, v.z, v.w};
#pragma unroll
    for (int j = 0; j < 4; j++) {
        __nv_bfloat16 hb = __float2bfloat16_rn(f[j]);
        h[j] = __bfloat16_as_ushort(hb);
        l[j] = __bfloat16_as_ushort(__float2bfloat16_rn(f[j] - __bfloat162float(hb)));
    }
    *(uint2*)(hi + (size_t)i * 4) = make_uint2((uint32)h[0] | ((uint32)h[1] << 16),
                                               (uint32)h[2] | ((uint32)h[3] << 16));
    *(uint2*)(lo + (size_t)i * 4) = make_uint2((uint32)l[0] | ((uint32)l[1] << 16),
                                               (uint32)l[2] | ((uint32)l[3] << 16));
}

#define BST 12
#define MATW (128 * BST)
#define BFS_SMEM (8 * MATW * 4)

__device__ __forceinline__ void cvt_hl(float x, unsigned short& h, unsigned short& l) {
    __nv_bfloat16 hb = __float2bfloat16_rn(x);
    h = __bfloat16_as_ushort(hb);
    l = __bfloat16_as_ushort(__float2bfloat16_rn(x - __bfloat162float(hb)));
}

// ---------------- split-bf16 TC GEMM N=128 (xg2) ----------------
__global__ void __launch_bounds__(256) gemm_bfs(const float* __restrict__ A,
                                                const ushort_* __restrict__ Bhi,
                                                const ushort_* __restrict__ Blo,
                                                float* __restrict__ C, int N) {
    extern __shared__ __align__(16) uint32 bsm[];
    uint32* Ah = bsm;
    uint32* Al = bsm + 2 * MATW;
    uint32* Bh = bsm + 4 * MATW;
    uint32* Bl = bsm + 6 * MATW;

    int tid = threadIdx.x;
    int m0 = blockIdx.y * 128, n0 = blockIdx.x * 128;
    int wid = tid >> 5, l = tid & 31;
    int wm = wid & 3, wn = wid >> 2;
    const float* Ag = A + (size_t)m0 * 256;
    const ushort_* Bhg = Bhi + (size_t)n0 * 256;
    const ushort_* Blg = Blo + (size_t)n0 * 256;

    float c[16][4];
#pragma unroll
    for (int i = 0; i < 16; i++)
#pragma unroll
        for (int j = 0; j < 4; j++) c[i][j] = 0.f;

    int lrow = tid >> 1, lhalf = tid & 1;
    size_t bsrc = (size_t)lrow * 256 + lhalf * 8;
    int bdst = lrow * BST + lhalf * 4;

    float4 av[2];
    uint4 vbh, vbl;
#pragma unroll
    for (int j = 0; j < 2; j++) {
        int f = tid + j * 256; int row = f >> 2, q = f & 3;
        av[j] = *(const float4*)(Ag + (size_t)row * 256 + q * 4);
    }
    vbh = *(const uint4*)(Bhg + bsrc);
    vbl = *(const uint4*)(Blg + bsrc);
#pragma unroll
    for (int j = 0; j < 2; j++) {
        int f = tid + j * 256; int row = f >> 2, q = f & 3;
        unsigned short h0, h1, h2, h3, l0, l1, l2, l3;
        cvt_hl(av[j].x, h0, l0); cvt_hl(av[j].y, h1, l1);
        cvt_hl(av[j].z, h2, l2); cvt_hl(av[j].w, h3, l3);
        Ah[row * BST + q * 2]     = (uint32)h0 | ((uint32)h1 << 16);
        Ah[row * BST + q * 2 + 1] = (uint32)h2 | ((uint32)h3 << 16);
        Al[row * BST + q * 2]     = (uint32)l0 | ((uint32)l1 << 16);
        Al[row * BST + q * 2 + 1] = (uint32)l2 | ((uint32)l3 << 16);
    }
    *(uint4*)&Bh[bdst] = vbh;
    *(uint4*)&Bl[bdst] = vbl;
    __syncthreads();

    int fr = l >> 2, kp = l & 3;
    for (int ch = 0; ch < 16; ch++) {
        int cur = ch & 1;
        uint32* Ahc = Ah + cur * MATW;
        uint32* Alc = Al + cur * MATW;
        uint32* Bhc = Bh + cur * MATW;
        uint32* Blc = Bl + cur * MATW;
        if (ch < 15) {
#pragma unroll
            for (int j = 0; j < 2; j++) {
                int f = tid + j * 256; int row = f >> 2, q = f & 3;
                av[j] = *(const float4*)(Ag + (size_t)row * 256 + (ch + 1) * 16 + q * 4);
            }
            vbh = *(const uint4*)(Bhg + bsrc + (ch + 1) * 16);
            vbl = *(const uint4*)(Blg + bsrc + (ch + 1) * 16);
        }
        uint32 ah[2][4], al_[2][4];
#pragma unroll
        for (int mi = 0; mi < 2; mi++) {
            int r = wm * 32 + mi * 16 + fr;
            ah[mi][0] = Ahc[r * BST + kp];
            ah[mi][1] = Ahc[(r + 8) * BST + kp];
            ah[mi][2] = Ahc[r * BST + 4 + kp];
            ah[mi][3] = Ahc[(r + 8) * BST + 4 + kp];
            al_[mi][0] = Alc[r * BST + kp];
            al_[mi][1] = Alc[(r + 8) * BST + kp];
            al_[mi][2] = Alc[r * BST + 4 + kp];
            al_[mi][3] = Alc[(r + 8) * BST + 4 + kp];
        }
#pragma unroll
        for (int ni = 0; ni < 8; ni++) {
            int nr = wn * 64 + ni * 8 + fr;
            uint32 bh0 = Bhc[nr * BST + kp];
            uint32 bh1 = Bhc[nr * BST + 4 + kp];
            uint32 bl0 = Blc[nr * BST + kp];
            uint32 bl1 = Blc[nr * BST + 4 + kp];
#pragma unroll
            for (int mi = 0; mi < 2; mi++) {
                MMA16816(c[mi * 8 + ni], ah[mi][0], ah[mi][1], ah[mi][2], ah[mi][3], bh0, bh1);
                MMA16816(c[mi * 8 + ni], ah[mi][0], ah[mi][1], ah[mi][2], ah[mi][3], bl0, bl1);
                MMA16816(c[mi * 8 + ni], al_[mi][0], al_[mi][1], al_[mi][2], al_[mi][3], bh0, bh1);
            }
        }
        if (ch < 15) {
            int nxt = cur ^ 1;
            uint32* Ahn = Ah + nxt * MATW;
            uint32* Aln = Al + nxt * MATW;
#pragma unroll
            for (int j = 0; j < 2; j++) {
                int f = tid + j * 256; int row = f >> 2, q = f & 3;
                unsigned short h0, h1, h2, h3, l0, l1, l2, l3;
                cvt_hl(av[j].x, h0, l0); cvt_hl(av[j].y, h1, l1);
                cvt_hl(av[j].z, h2, l2); cvt_hl(av[j].w, h3, l3);
                Ahn[row * BST + q * 2]     = (uint32)h0 | ((uint32)h1 << 16);
                Ahn[row * BST + q * 2 + 1] = (uint32)h2 | ((uint32)h3 << 16);
                Aln[row * BST + q * 2]     = (uint32)l0 | ((uint32)l1 << 16);
                Aln[row * BST + q * 2 + 1] = (uint32)l2 | ((uint32)l3 << 16);
            }
            *(uint4*)&Bh[nxt * MATW + bdst] = vbh;
            *(uint4*)&Bl[nxt * MATW + bdst] = vbl;
            __syncthreads();
        }
    }
#pragma unroll
    for (int mi = 0; mi < 2; mi++)
#pragma unroll
        for (int ni = 0; ni < 8; ni++) {
            int row = m0 + wm * 32 + mi * 16 + fr;
            int col = n0 + wn * 64 + ni * 8 + kp * 2;
            float2* p0 = (float2*)(C + (size_t)row * N + col);
            float2* p1 = (float2*)(C + (size_t)(row + 8) * N + col);
            *p0 = make_float2(c[mi * 8 + ni][0], c[mi * 8 + ni][1]);
            *p1 = make_float2(c[mi * 8 + ni][2], c[mi * 8 + ni][3]);
        }
}

// ---------------- split-bf16 TC GEMM N=64 (head) ----------------
#define MATWB64 (64 * BST)
#define BFS64_SMEM ((4 * MATW + 4 * MATWB64) * 4)
__global__ void __launch_bounds__(256) gemm_bfs64(const float* __restrict__ A,
                                                  const ushort_* __restrict__ Bhi,
                                                  const ushort_* __restrict__ Blo,
                                                  float* __restrict__ C) {
    extern __shared__ __align__(16) uint32 bsm[];
    uint32* Ah = bsm;
    uint32* Al = bsm + 2 * MATW;
    uint32* Bh = bsm + 4 * MATW;
    uint32* Bl = bsm + 4 * MATW + 2 * MATWB64;

    int tid = threadIdx.x;
    int m0 = blockIdx.y * 128;
    int wid = tid >> 5, l = tid & 31;
    int wm = wid & 3, wn = wid >> 2;   // 4(m) x 2(n): warp tile 32m x 32n
    const float* Ag = A + (size_t)m0 * 256;

    float c[8][4];
#pragma unroll
    for (int i = 0; i < 8; i++)
#pragma unroll
        for (int j = 0; j < 4; j++) c[i][j] = 0.f;

    int lrow = tid >> 1, lhalf = tid & 1;   // B loader: tid<128 covers 64 rows
    size_t bsrc = (size_t)lrow * 256 + lhalf * 8;
    int bdst = lrow * BST + lhalf * 4;

    float4 av[2];
    uint4 vbh, vbl;
#pragma unroll
    for (int j = 0; j < 2; j++) {
        int f = tid + j * 256; int row = f >> 2, q = f & 3;
        av[j] = *(const float4*)(Ag + (size_t)row * 256 + q * 4);
    }
    if (tid < 128) {
        vbh = *(const uint4*)(Bhi + bsrc);
        vbl = *(const uint4*)(Blo + bsrc);
    }
#pragma unroll
    for (int j = 0; j < 2; j++) {
        int f = tid + j * 256; int row = f >> 2, q = f & 3;
        unsigned short h0, h1, h2, h3, l0, l1, l2, l3;
        cvt_hl(av[j].x, h0, l0); cvt_hl(av[j].y, h1, l1);
        cvt_hl(av[j].z, h2, l2); cvt_hl(av[j].w, h3, l3);
        Ah[row * BST + q * 2]     = (uint32)h0 | ((uint32)h1 << 16);
        Ah[row * BST + q * 2 + 1] = (uint32)h2 | ((uint32)h3 << 16);
        Al[row * BST + q * 2]     = (uint32)l0 | ((uint32)l1 << 16);
        Al[row * BST + q * 2 + 1] = (uint32)l2 | ((uint32)l3 << 16);
    }
    if (tid < 128) {
        *(uint4*)&Bh[bdst] = vbh;
        *(uint4*)&Bl[bdst] = vbl;
    }
    __syncthreads();

    int fr = l >> 2, kp = l & 3;
    for (int ch = 0; ch < 16; ch++) {
        int cur = ch & 1;
        uint32* Ahc = Ah + cur * MATW;
        uint32* Alc = Al + cur * MATW;
        uint32* Bhc = Bh + cur * MATWB64;
        uint32* Blc = Bl + cur * MATWB64;
        if (ch < 15) {
#pragma unroll
            for (int j = 0; j < 2; j++) {
                int f = tid + j * 256; int row = f >> 2, q = f & 3;
                av[j] = *(const float4*)(Ag + (size_t)row * 256 + (ch + 1) * 16 + q * 4);
            }
            if (tid < 128) {
                vbh = *(const uint4*)(Bhi + bsrc + (ch + 1) * 16);
                vbl = *(const uint4*)(Blo + bsrc + (ch + 1) * 16);
            }
        }
        uint32 ah[2][4], al_[2][4];
#pragma unroll
        for (int mi = 0; mi < 2; mi++) {
            int r = wm * 32 + mi * 16 + fr;
            ah[mi][0] = Ahc[r * BST + kp];
            ah[mi][1] = Ahc[(r + 8) * BST + kp];
            ah[mi][2] = Ahc[r * BST + 4 + kp];
            ah[mi][3] = Ahc[(r + 8) * BST + 4 + kp];
            al_[mi][0] = Alc[r * BST + kp];
            al_[mi][1] = Alc[(r + 8) * BST + kp];
            al_[mi][2] = Alc[r * BST + 4 + kp];
            al_[mi][3] = Alc[(r + 8) * BST + 4 + kp];
        }
#pragma unroll
        for (int ni = 0; ni < 4; ni++) {
            int nr = wn * 32 + ni * 8 + fr;
            uint32 bh0 = Bhc[nr * BST + kp];
            uint32 bh1 = Bhc[nr * BST + 4 + kp];
            uint32 bl0 = Blc[nr * BST + kp];
            uint32 bl1 = Blc[nr * BST + 4 + kp];
#pragma unroll
            for (int mi = 0; mi < 2; mi++) {
                MMA16816(c[mi * 4 + ni], ah[mi][0], ah[mi][1], ah[mi][2], ah[mi][3], bh0, bh1);
                MMA16816(c[mi * 4 + ni], ah[mi][0], ah[mi][1], ah[mi][2], ah[mi][3], bl0, bl1);
                MMA16816(c[mi * 4 + ni], al_[mi][0], al_[mi][1], al_[mi][2], al_[mi][3], bh0, bh1);
            }
        }
        if (ch < 15) {
            int nxt = cur ^ 1;
            uint32* Ahn = Ah + nxt * MATW;
            uint32* Aln = Al + nxt * MATW;
#pragma unroll
            for (int j = 0; j < 2; j++) {
                int f = tid + j * 256; int row = f >> 2, q = f & 3;
                unsigned short h0, h1, h2, h3, l0, l1, l2, l3;
                cvt_hl(av[j].x, h0, l0); cvt_hl(av[j].y, h1, l1);
                cvt_hl(av[j].z, h2, l2); cvt_hl(av[j].w, h3, l3);
                Ahn[row * BST + q * 2]     = (uint32)h0 | ((uint32)h1 << 16);
                Ahn[row * BST + q * 2 + 1] = (uint32)h2 | ((uint32)h3 << 16);
                Aln[row * BST + q * 2]     = (uint32)l0 | ((uint32)l1 << 16);
                Aln[row * BST + q * 2 + 1] = (uint32)l2 | ((uint32)l3 << 16);
            }
            if (tid < 128) {
                *(uint4*)&Bh[nxt * MATWB64 + bdst] = vbh;
                *(uint4*)&Bl[nxt * MATWB64 + bdst] = vbl;
            }
            __syncthreads();
        }
    }
#pragma unroll
    for (int mi = 0; mi < 2; mi++)
#pragma unroll
        for (int ni = 0; ni < 4; ni++) {
            int row = m0 + wm * 32 + mi * 16 + fr;
            int col = wn * 32 + ni * 8 + kp * 2;
            float2* p0 = (float2*)(C + (size_t)row * NS_ + col);
            float2* p1 = (float2*)(C + (size_t)(row + 8) * NS_ + col);
            *p0 = make_float2(c[mi * 4 + ni][0], c[mi * 4 + ni][1]);
            *p1 = make_float2(c[mi * 4 + ni][2], c[mi * 4 + ni][3]);
        }
}

// ---------------- GEMM 128x128 fp32 (emb-proj only) ----------------
#define GS 132
__global__ void __launch_bounds__(256) gemm128(const float* __restrict__ A,
                                               const float* __restrict__ Bm,
                                               float* __restrict__ C, int N) {
    __shared__ __align__(16) float As[2][16 * GS];
    __shared__ __align__(16) float Bs[2][16 * GS];
    int tid = threadIdx.x;
    int m0 = blockIdx.y * 128, n0 = blockIdx.x * 128;
    int tm = tid & 15, tn = tid >> 4;
    const float* Ag = A + (size_t)m0 * 256;
    const float* Bg = Bm + (size_t)n0 * 256;

    float4 ar[2], br[2];
#pragma unroll
    for (int j = 0; j < 2; j++) {
        int f = tid + j * 256;
        ar[j] = *(const float4*)(Ag + (size_t)(f >> 2) * 256 + (f & 3) * 4);
        br[j] = *(const float4*)(Bg + (size_t)(f >> 2) * 256 + (f & 3) * 4);
    }
#pragma unroll
    for (int j = 0; j < 2; j++) {
        int f = tid + j * 256; int row = f >> 2, kq = f & 3;
        As[0][(kq * 4 + 0) * GS + row] = ar[j].x;
        As[0][(kq * 4 + 1) * GS + row] = ar[j].y;
        As[0][(kq * 4 + 2) * GS + row] = ar[j].z;
        As[0][(kq * 4 + 3) * GS + row] = ar[j].w;
        Bs[0][(kq * 4 + 0) * GS + row] = br[j].x;
        Bs[0][(kq * 4 + 1) * GS + row] = br[j].y;
        Bs[0][(kq * 4 + 2) * GS + row] = br[j].z;
        Bs[0][(kq * 4 + 3) * GS + row] = br[j].w;
    }
    __syncthreads();

    ull acc[4][8];
#pragma unroll
    for (int i = 0; i < 4; i++)
#pragma unroll
        for (int j = 0; j < 8; j++) acc[i][j] = 0ull;

    for (int ch = 0; ch < 16; ch++) {
        int cur = ch & 1;
        if (ch < 15) {
#pragma unroll
            for (int j = 0; j < 2; j++) {
                int f = tid + j * 256;
                ar[j] = *(const float4*)(Ag + (size_t)(f >> 2) * 256 + (ch + 1) * 16 + (f & 3) * 4);
                br[j] = *(const float4*)(Bg + (size_t)(f >> 2) * 256 + (ch + 1) * 16 + (f & 3) * 4);
            }
        }
#pragma unroll
        for (int k = 0; k < 16; k++) {
            ulonglong2 a01 = *(const ulonglong2*)&As[cur][k * GS + tm * 8];
            ulonglong2 a23 = *(const ulonglong2*)&As[cur][k * GS + tm * 8 + 4];
            float4 bq0 = *(const float4*)&Bs[cur][k * GS + tn * 8];
            float4 bq1 = *(const float4*)&Bs[cur][k * GS + tn * 8 + 4];
            float bf[8] = {bq0.x, bq0.y, bq0.z, bq0.w, bq1.x, bq1.y, bq1.z, bq1.w};
#pragma unroll
            for (int j = 0; j < 8; j++) {
                ull bb = dup2(bf[j]);
                acc[0][j] = ffma2(a01.x, bb, acc[0][j]);
                acc[1][j] = ffma2(a01.y, bb, acc[1][j]);
                acc[2][j] = ffma2(a23.x, bb, acc[2][j]);
                acc[3][j] = ffma2(a23.y, bb, acc[3][j]);
            }
        }
        if (ch < 15) {
            int nxt = cur ^ 1;
#pragma unroll
            for (int j = 0; j < 2; j++) {
                int f = tid + j * 256; int row = f >> 2, kq = f & 3;
                As[nxt][(kq * 4 + 0) * GS + row] = ar[j].x;
                As[nxt][(kq * 4 + 1) * GS + row] = ar[j].y;
                As[nxt][(kq * 4 + 2) * GS + row] = ar[j].z;
                As[nxt][(kq * 4 + 3) * GS + row] = ar[j].w;
                Bs[nxt][(kq * 4 + 0) * GS + row] = br[j].x;
                Bs[nxt][(kq * 4 + 1) * GS + row] = br[j].y;
                Bs[nxt][(kq * 4 + 2) * GS + row] = br[j].z;
                Bs[nxt][(kq * 4 + 3) * GS + row] = br[j].w;
            }
            __syncthreads();
        }
    }
#pragma unroll
    for (int i = 0; i < 8; i++) {
        int mp = i >> 1;
        float4 v0, v1;
        if ((i & 1) == 0) {
            v0.x = lo32(acc[mp][0]); v0.y = lo32(acc[mp][1]);
            v0.z = lo32(acc[mp][2]); v0.w = lo32(acc[mp][3]);
            v1.x = lo32(acc[mp][4]); v1.y = lo32(acc[mp][5]);
            v1.z = lo32(acc[mp][6]); v1.w = lo32(acc[mp][7]);
        } else {
            v0.x = hi32(acc[mp][0]); v0.y = hi32(acc[mp][1]);
            v0.z = hi32(acc[mp][2]); v0.w = hi32(acc[mp][3]);
            v1.x = hi32(acc[mp][4]); v1.y = hi32(acc[mp][5]);
            v1.z = hi32(acc[mp][6]); v1.w = hi32(acc[mp][7]);
        }
        float* cp = C + (size_t)(m0 + tm * 8 + i) * N + n0 + tn * 8;
        *(float4*)cp = v0;
        *(float4*)(cp + 4) = v1;
    }
}

// ---------------- GRU recurrence: R12 best (byte-identical) ----------
#define CL_ 8
#define RW_ 8
#define HB_OFF   0
#define PART_OFF 4096
#define IDS_OFF  10240
#define MBAR_OFF 14336
#define SMEM_RECUR ((MBAR_OFF + 4) * 4)

__global__ void __launch_bounds__(256, 1) __cluster_dims__(CL_, 1, 1)
gru_recur(const float* __restrict__ whh, const float* __restrict__ bhh_g,
          const float* __restrict__ bih_g, const float* __restrict__ xgsrc,
          const int* __restrict__ ids_g, const float* __restrict__ embp,
          float* __restrict__ hout, int layer) {
    extern __shared__ __align__(16) float sm[];
    float* hb = sm + HB_OFF;
    float* part = sm + PART_OFF;
    int* ids_s = (int*)(sm + IDS_OFF);
    unsigned mbar_a = smem_u32(sm + MBAR_OFF);

    int tid = threadIdx.x;
    unsigned rank;
    asm("mov.u32 %0, %%cluster_ctarank;" : "=r"(rank));
    int cid = blockIdx.x >> 3;
    int d0 = rank * 32;
    int brow0 = cid * RW_;
    int w = tid >> 5, l = tid & 31;

    ull wreg[3][16];
#pragma unroll
    for (int g = 0; g < 3; g++) {
        const float* wrow = whh + (size_t)(g * 256 + d0 + l) * 256 + w * 32;
#pragma unroll
        for (int kp = 0; kp < 16; kp++)
            wreg[g][kp] = *(const ull*)(wrow + 2 * kp);
    }

    for (int i = tid; i < 2 * RW_ * 256; i += 256) hb[i] = 0.f;
    if (layer == 0)
        for (int i = tid; i < RW_ * T_; i += 256) ids_s[i] = ids_g[brow0 * T_ + i];
    if (tid == 0)
        asm volatile("mbarrier.init.shared::cta.b64 [%0], 8;" :: "r"(mbar_a) : "memory");

    int erw = w, edj = l;
    int dfull = d0 + edj;
    float bhr = bhh_g[dfull], bhz = bhh_g[256 + dfull], bhn = bhh_g[512 + dfull];
    float bir = bih_g[dfull], biz = bih_g[256 + dfull], bin_ = bih_g[512 + dfull];

    unsigned hb_local = smem_u32(hb);
    unsigned peer_hb[CL_], peer_mb[CL_];
#pragma unroll
    for (int r = 0; r < CL_; r++) {
        asm("mapa.shared::cluster.u32 %0, %1, %2;" : "=r"(peer_hb[r]) : "r"(hb_local), "r"(r));
        asm("mapa.shared::cluster.u32 %0, %1, %2;" : "=r"(peer_mb[r]) : "r"(mbar_a), "r"(r));
    }
    int pr = (l < 7) ? (l + (l >= (int)rank ? 1 : 0)) : 0;
    unsigned my_peer_hb = peer_hb[pr], my_peer_mb = peer_mb[pr];

    __syncthreads();
    cluster_sync_();

    for (int t = 0; t < T_; t++) {
        int p = t & 1;
        float* hcur = hb + p * 2048;

        float xr, xz, xn;
        if (layer == 0) {
            int id = ids_s[erw * T_ + t];
            const float* e = embp + (size_t)id * G_ + dfull;
            xr = __ldg(e); xz = __ldg(e + 256); xn = __ldg(e + 512);
        } else {
            const float* e = xgsrc + ((size_t)(brow0 + erw) * T_ + t) * G_ + dfull;
            xr = __ldg(e); xz = __ldg(e + 256); xn = __ldg(e + 512);
        }

        ull acc0[8], acc1[8], acc2_[8];
#pragma unroll
        for (int r = 0; r < 8; r++) { acc0[r] = 0ull; acc1[r] = 0ull; acc2_[r] = 0ull; }
        const float* hblk = hcur + w * 256;
#pragma unroll
        for (int it = 0; it < 8; it++) {
            ulonglong2 h4[8];
#pragma unroll
            for (int r = 0; r < 8; r++)
                h4[r] = *(const ulonglong2*)(hblk + r * 32 + (it << 2));
#pragma unroll
            for (int s = 0; s < 2; s++) {
                ull w0 = wreg[0][2 * it + s];
                ull w1 = wreg[1][2 * it + s];
                ull w2v = wreg[2][2 * it + s];
#pragma unroll
                for (int r = 0; r < 8; r++) {
                    ull hh = s ? h4[r].y : h4[r].x;
                    acc0[r] = ffma2(w0, hh, acc0[r]);
                    acc1[r] = ffma2(w1, hh, acc1[r]);
                    acc2_[r] = ffma2(w2v, hh, acc2_[r]);
                }
            }
        }
#pragma unroll
        for (int r = 0; r < 8; r++) {
            part[w * 768 + r * 96 + l]      = lo32(acc0[r]) + hi32(acc0[r]);
            part[w * 768 + r * 96 + 32 + l] = lo32(acc1[r]) + hi32(acc1[r]);
            part[w * 768 + r * 96 + 64 + l] = lo32(acc2_[r]) + hi32(acc2_[r]);
        }
        __syncthreads();

        float rs = 0.f, zs = 0.f, ns = 0.f;
#pragma unroll
        for (int kg = 0; kg < 8; kg++) {
            const float* pp = part + kg * 768 + erw * 96 + edj;
            rs += pp[0]; zs += pp[32]; ns += pp[64];
        }
        float hprev = hcur[rank * 256 + erw * 32 + edj];
        float rr = 0.5f + 0.5f * tanhapx(0.5f * (xr + bir + rs + bhr));
        float zz = 0.5f + 0.5f * tanhapx(0.5f * (xz + biz + zs + bhz));
        float nn = tanhapx(xn + bin_ + rr * (ns + bhn));
        float hn = (1.f - zz) * nn + zz * hprev;

        hout[((size_t)(brow0 + erw) * T_ + t) * 256 + dfull] = hn;
        unsigned row_off = (unsigned)((((p ^ 1) * 2048) + rank * 256 + erw * 32) * 4);
        hb[((p ^ 1) * 2048) + rank * 256 + erw * 32 + edj] = hn;
        __syncwarp();
        if (l < 7) {
            asm volatile("fence.proxy.async.shared::cta;" ::: "memory");
            asm volatile("cp.async.bulk.shared::cluster.shared::cta.mbarrier::complete_tx::bytes [%0], [%1], %2, [%3];"
                         :: "r"(my_peer_hb + row_off), "r"(hb_local + row_off), "r"(128), "r"(my_peer_mb) : "memory");
        }
        if (l == 0) {
            if (w == 0)
                asm volatile("mbarrier.arrive.expect_tx.shared::cta.b64 _, [%0], %1;"
                             :: "r"(mbar_a), "r"(7168) : "memory");
            else
                asm volatile("mbarrier.arrive.shared::cta.b64 _, [%0];"
                             :: "r"(mbar_a) : "memory");
        }
        asm volatile("{\n\t.reg .pred P;\n\tWL_%=:\n\tmbarrier.try_wait.parity.acquire.cta.shared::cta.b64 P, [%0], %1;\n\t@!P bra WL_%=;\n\t}\n"
                     :: "r"(mbar_a), "r"(p) : "memory");
    }
    cluster_sync_();
}

// ---------------- masked cross-entropy loss ----------------
__global__ void __launch_bounds__(256) loss_partial_kernel(const float* __restrict__ logits,
                                                           const int* __restrict__ targets,
                                                           const void* __restrict__ maskp,
                                                           float2* __restrict__ partials) {
    __shared__ float s1[256], s2[256];
    int tid = threadIdx.x;
    int i = blockIdx.x * 256 + tid;
    const float* lg = logits + (size_t)i * NS_;
    float mx = -1e30f;
#pragma unroll 8
    for (int j = 0; j < NS_; j++) mx = fmaxf(mx, lg[j]);
    float s = 0.f;
#pragma unroll 8
    for (int j = 0; j < NS_; j++) s += expf(lg[j] - mx);
    float nll = mx + logf(s) - lg[targets[i]];
    float m;
    int mode = g_mask_mode;
    if (mode == 0)      m = (float)((const int*)maskp)[i];
    else if (mode == 1) m = ((const float*)maskp)[i];
    else                m = (float)((const unsigned char*)maskp)[i];
    s1[tid] = nll * m;
    s2[tid] = m;
    __syncthreads();
    for (int o = 128; o; o >>= 1) {
        if (tid < o) { s1[tid] += s1[tid + o]; s2[tid] += s2[tid + o]; }
        __syncthreads();
    }
    if (tid == 0) partials[blockIdx.x] = make_float2(s1[0], s2[0]);
}

__global__ void __launch_bounds__(256) loss_final_kernel(const float2* __restrict__ partials,
                                                         float* __restrict__ out, int out_size) {
    __shared__ float s1[256], s2[256];
    int tid = threadIdx.x;
    float2 v = partials[tid];
    s1[tid] = v.x; s2[tid] = v.y;
    __syncthreads();
    for (int o = 128; o; o >>= 1) {
        if (tid < o) { s1[tid] += s1[tid + o]; s2[tid] += s2[tid + o]; }
        __syncthreads();
    }
    float msum = s2[0];
    float loss = (msum > 0.f) ? s1[0] / fmaxf(msum, 1.f) : 0.f;
    int start = (out_size >= BTN_) ? BTN_ : 0;
    for (int i = start + tid; i < out_size; i += 256) out[i] = loss;
}

// ---------------- launcher ----------------
extern "C" void kernel_launch(void* const* d_in, const int* in_sizes, int n_in,
                              void* d_out, int out_size) {
    const int* ids = (const int*)d_in[0];
    const int* tgt = (const int*)d_in[1];
    const void* mask = d_in[2];
    const float* emb = (const float*)d_in[3];
    const float* wih = (const float*)d_in[4];
    const float* whh = (const float*)d_in[5];
    const float* bih = (const float*)d_in[6];
    const float* bhh = (const float*)d_in[7];
    const float* hw  = (const float*)d_in[8];
    float* out = (float*)d_out;

    float *embp, *xg2, *h1, *h2; float2* lpart;
    ushort_ *wihhi, *wihlo, *hwhi, *hwlo;
    cudaGetSymbolAddress((void**)&embp, d_emb_proj);
    cudaGetSymbolAddress((void**)&xg2, d_xg2);
    cudaGetSymbolAddress((void**)&h1, d_h1);
    cudaGetSymbolAddress((void**)&h2, d_h2);
    cudaGetSymbolAddress((void**)&wihhi, d_wihhi);
    cudaGetSymbolAddress((void**)&wihlo, d_wihlo);
    cudaGetSymbolAddress((void**)&hwhi, d_hwhi);
    cudaGetSymbolAddress((void**)&hwlo, d_hwlo);
    cudaGetSymbolAddress((void**)&lpart, d_lpart);

    cudaFuncSetAttribute(gru_recur, cudaFuncAttributeMaxDynamicSharedMemorySize, SMEM_RECUR);
    cudaFuncSetAttribute(gemm_bfs, cudaFuncAttributeMaxDynamicSharedMemorySize, BFS_SMEM);
    cudaFuncSetAttribute(gemm_bfs64, cudaFuncAttributeMaxDynamicSharedMemorySize, BFS64_SMEM);

    probe_mask_kernel<<<1, 32>>>((const unsigned char*)mask);
    gemm128<<<dim3(6, 4), 256>>>(emb, wih, embp, G_);
    cvt_split<<<(G_ * 256 / 4 + 255) / 256, 256>>>(wih + 768 * 256, wihhi, wihlo, G_ * 256 / 4);
    cvt_split<<<(NS_ * 256 / 4 + 255) / 256, 256>>>(hw, hwhi, hwlo, NS_ * 256 / 4);
    gru_recur<<<128, 256, SMEM_RECUR>>>(whh, bhh, bih, (const float*)0, ids, embp, h1, 0);
    gemm_bfs<<<dim3(6, 512), 256, BFS_SMEM>>>(h1, wihhi, wihlo, xg2, G_);
    gru_recur<<<128, 256, SMEM_RECUR>>>(whh + 768 * 256, bhh + 768, bih + 768, xg2, ids, embp, h2, 1);
    float* ldst = (out_size >= BTN_) ? out : xg2;
    gemm_bfs64<<<dim3(1, 512), 256, BFS64_SMEM>>>(h2, hwhi, hwlo, ldst);
    loss_partial_kernel<<<256, 256>>>(ldst, tgt, mask, lpart);
    loss_final_kernel<<<1, 256>>>(lpart, out, out_size);
}